// round 2
// baseline (speedup 1.0000x reference)
#include <cuda_runtime.h>
#include <math.h>

// ---------------------------------------------------------------------------
// Problem constants
// ---------------------------------------------------------------------------
#define B_SZ    32
#define T_LEN   2048
#define D_DIM   512
#define HH      64
#define S_STEPS 3
#define N_ELEM  (B_SZ * T_LEN)          // 65536
#define ROW_W   (2 * D_DIM + 1)         // 1025

// Flow kernel config
#define NT        256
#define GRID_FLOW 128
#define E_STRIDE  (GRID_FLOW * NT)      // 32768; each thread handles e and e+32768

// Shared layout (float offsets). Weights transposed, row stride 68 floats
// (272 B, 16B-aligned -> LDS.128 weight loads; broadcast so conflicts moot).
#define WROW     68
#define WMAT     (HH * WROW)            // 4352
#define OFF_W1T  0                      // 2 blocks
#define OFF_W2T  (2 * WMAT)             // 8704
#define OFF_WC0  (4 * WMAT)             // 17408
#define OFF_B0   (OFF_WC0 + 64)
#define OFF_B1   (OFF_B0 + 64)
#define OFF_B2   (OFF_B1 + 128)
#define OFF_WCB  (OFF_B2 + 128)
#define OFF_BCB  (OFF_WCB + 128)
#define OFF_WF   (OFF_BCB + 128)
#define OFF_BF   (OFF_WF + 128)
#define OFF_HBUF (OFF_BF + 16)          // 18192
#define SMEM_FLOATS (OFF_HBUF + HH * NT)            // 34576
#define SMEM_BYTES  (SMEM_FLOATS * sizeof(float))   // 138,304 B

// ---------------------------------------------------------------------------
// Packed fp32x2 helpers (Blackwell FFMA2 path — only reachable via PTX)
// ---------------------------------------------------------------------------
typedef unsigned long long u64t;

__device__ __forceinline__ u64t fma2(u64t a, u64t b, u64t c) {
    u64t d;
    asm("fma.rn.f32x2 %0, %1, %2, %3;" : "=l"(d) : "l"(a), "l"(b), "l"(c));
    return d;
}
__device__ __forceinline__ u64t pack2(float x, float y) {
    u64t r; asm("mov.b64 %0, {%1, %2};" : "=l"(r) : "f"(x), "f"(y)); return r;
}
__device__ __forceinline__ float2 unpack2(u64t v) {
    float2 r; asm("mov.b64 {%0, %1}, %2;" : "=f"(r.x), "=f"(r.y) : "l"(v)); return r;
}

// ---------------------------------------------------------------------------
// Flow kernel: per-element normalizing-flow log_prob
// out[e*1025 + 1024] = -0.5*z^2 - 0.5*log(2pi) + logdet
// ---------------------------------------------------------------------------
__global__ void __launch_bounds__(NT, 1)
flow_kernel(const float* __restrict__ residual,
            const float* __restrict__ gbinit, const float* __restrict__ gWc0,
            const float* __restrict__ gbc0,
            const float* __restrict__ gW1,   const float* __restrict__ gb1,
            const float* __restrict__ gW2,   const float* __restrict__ gb2,
            const float* __restrict__ gWcb,  const float* __restrict__ gbcb,
            const float* __restrict__ gWf,   const float* __restrict__ gbf,
            float* __restrict__ out)
{
    extern __shared__ float sm[];
    const int tid = threadIdx.x;
    float* hcol = sm + OFF_HBUF + tid;   // this thread's private h column

    float cv[2], zv[2], ldet[2];
#pragma unroll
    for (int k = 0; k < 2; k++) {
        const int e = blockIdx.x * NT + tid + k * E_STRIDE;
        zv[k]   = residual[e];
        cv[k]   = ((e & (T_LEN - 1)) == 0) ? 0.0f : residual[e - 1];
        ldet[k] = 0.0f;
    }

    for (int s = 0; s < S_STEPS; s++) {
        __syncthreads();   // previous step's reads done before overwrite
        // --- cooperative staging of this step's weights (transposed) ---
        for (int idx = tid; idx < 16384; idx += NT) {
            const int which = idx >> 13;              // 0: W1, 1: W2
            const int r   = idx & 8191;
            const int blk = r >> 12;
            const int rr  = r & 4095;
            const int i   = rr >> 6;                  // output index
            const int j   = rr & 63;                  // input index
            const float v = which ? gW2[s * 8192 + r] : gW1[s * 8192 + r];
            sm[(which ? OFF_W2T : OFF_W1T) + blk * WMAT + j * WROW + i] = v;
        }
        if (tid < 64) {
            sm[OFF_WC0 + tid] = gWc0[s * 64 + tid];
            sm[OFF_B0  + tid] = gbc0[s * 64 + tid] + gbinit[s * 64 + tid];
        }
        if (tid < 128) {
            sm[OFF_B1  + tid] = gb1 [s * 128 + tid];
            sm[OFF_B2  + tid] = gb2 [s * 128 + tid];
            sm[OFF_WCB + tid] = gWcb[s * 128 + tid];
            sm[OFF_BCB + tid] = gbcb[s * 128 + tid];
            sm[OFF_WF  + tid] = gWf [s * 128 + tid];
        }
        if (tid < 2) sm[OFF_BF + tid] = gbf[s * 2 + tid];
        __syncthreads();

#pragma unroll
        for (int k = 0; k < 2; k++) {
            const float cc = cv[k];
            // h = c * Wc0 + (bc0 + b_init)
#pragma unroll
            for (int i = 0; i < HH; i++)
                hcol[i * NT] = fmaf(cc, sm[OFF_WC0 + i], sm[OFF_B0 + i]);

            for (int blk = 0; blk < 2; blk++) {
                // ---- matvec1: t = relu(h) @ W1^T + b1 (packed accumulators) ----
                u64t t[32];
                {
                    const u64t* b1p = (const u64t*)(sm + OFF_B1 + blk * 64);
#pragma unroll
                    for (int q = 0; q < 32; q++) t[q] = b1p[q];
                    const float* W = sm + OFF_W1T + blk * WMAT;
#pragma unroll 4
                    for (int jj = 0; jj < HH; jj++) {
                        const float rh  = fmaxf(hcol[jj * NT], 0.0f);
                        const u64t  rh2 = pack2(rh, rh);
                        const ulonglong2* wr = (const ulonglong2*)(W + jj * WROW);
#pragma unroll
                        for (int q = 0; q < 16; q++) {
                            const ulonglong2 w = wr[q];
                            t[2 * q]     = fma2(rh2, w.x, t[2 * q]);
                            t[2 * q + 1] = fma2(rh2, w.y, t[2 * q + 1]);
                        }
                    }
                }
                // ---- matvec2: v = relu(t) @ W2^T + b2 (t stays in registers) ----
                u64t v[32];
                {
                    const u64t* b2p = (const u64t*)(sm + OFF_B2 + blk * 64);
#pragma unroll
                    for (int q = 0; q < 32; q++) v[q] = b2p[q];
                    const float* W = sm + OFF_W2T + blk * WMAT;
#pragma unroll 2
                    for (int q2 = 0; q2 < 32; q2++) {
                        const float2 tp = unpack2(t[q2]);
#pragma unroll
                        for (int h2 = 0; h2 < 2; h2++) {
                            const int   jj  = 2 * q2 + h2;
                            const float rt  = fmaxf(h2 ? tp.y : tp.x, 0.0f);
                            const u64t  rt2 = pack2(rt, rt);
                            const ulonglong2* wr = (const ulonglong2*)(W + jj * WROW);
#pragma unroll
                            for (int q = 0; q < 16; q++) {
                                const ulonglong2 w = wr[q];
                                v[2 * q]     = fma2(rt2, w.x, v[2 * q]);
                                v[2 * q + 1] = fma2(rt2, w.y, v[2 * q + 1]);
                            }
                        }
                    }
                }
                // ---- gate + residual: h += v * sigmoid(c*Wcb + bcb) ----
#pragma unroll
                for (int q = 0; q < 32; q++) {
                    const float2 vp = unpack2(v[q]);
                    const int i0 = 2 * q, i1 = 2 * q + 1;
                    const float g0 = fmaf(cc, sm[OFF_WCB + blk * 64 + i0],
                                          sm[OFF_BCB + blk * 64 + i0]);
                    const float g1 = fmaf(cc, sm[OFF_WCB + blk * 64 + i1],
                                          sm[OFF_BCB + blk * 64 + i1]);
                    const float s0 = __fdividef(1.0f, 1.0f + __expf(-g0));
                    const float s1 = __fdividef(1.0f, 1.0f + __expf(-g1));
                    hcol[i0 * NT] += vp.x * s0;
                    hcol[i1 * NT] += vp.y * s1;
                }
            }
            // ---- final linear (H -> 2), affine update of z ----
            float o0 = sm[OFF_BF + 0], o1 = sm[OFF_BF + 1];
#pragma unroll 4
            for (int j = 0; j < HH; j++) {
                const float rh = fmaxf(hcol[j * NT], 0.0f);
                o0 = fmaf(rh, sm[OFF_WF + j],      o0);
                o1 = fmaf(rh, sm[OFF_WF + 64 + j], o1);
            }
            const float sc = log1pf(__expf(o0)) + 1e-3f;   // softplus + 1e-3
            zv[k]   = fmaf(sc, zv[k], o1);
            ldet[k] += logf(sc);
        }
    }

#pragma unroll
    for (int k = 0; k < 2; k++) {
        const int e = blockIdx.x * NT + tid + k * E_STRIDE;
        const float lp = fmaf(-0.5f * zv[k], zv[k], ldet[k]) - 0.91893853320467274f;
        out[(size_t)e * ROW_W + 2 * D_DIM] = lp;
    }
}

// ---------------------------------------------------------------------------
// Feature kernel: out[row, 0:512]   = trend[row]*Wt + bt
//                 out[row, 512:1024]= seasonal[row]*Ws + bs
// ---------------------------------------------------------------------------
__global__ void __launch_bounds__(256)
feat_kernel(const float* __restrict__ trend, const float* __restrict__ seasonal,
            const float* __restrict__ Wt, const float* __restrict__ bt,
            const float* __restrict__ Ws, const float* __restrict__ bs,
            float* __restrict__ out)
{
    const int row = blockIdx.x;
    const int k   = threadIdx.x * 4;
    float sval;
    const float *W, *bb;
    int kk;
    if (k < D_DIM) { sval = trend[row];    W = Wt; bb = bt; kk = k; }
    else           { sval = seasonal[row]; W = Ws; bb = bs; kk = k - D_DIM; }
    const float4 w  = *(const float4*)(W  + kk);
    const float4 b4 = *(const float4*)(bb + kk);
    float* o = out + (size_t)row * ROW_W + k;
    o[0] = fmaf(sval, w.x, b4.x);
    o[1] = fmaf(sval, w.y, b4.y);
    o[2] = fmaf(sval, w.z, b4.z);
    o[3] = fmaf(sval, w.w, b4.w);
}

// ---------------------------------------------------------------------------
extern "C" void kernel_launch(void* const* d_in, const int* in_sizes, int n_in,
                              void* d_out, int out_size)
{
    const float* trend    = (const float*)d_in[0];
    const float* seasonal = (const float*)d_in[1];
    const float* residual = (const float*)d_in[2];
    const float* Wt    = (const float*)d_in[3];
    const float* bt    = (const float*)d_in[4];
    const float* Ws    = (const float*)d_in[5];
    const float* bs    = (const float*)d_in[6];
    const float* binit = (const float*)d_in[7];
    const float* Wc0   = (const float*)d_in[8];
    const float* bc0   = (const float*)d_in[9];
    const float* W1    = (const float*)d_in[10];
    const float* b1    = (const float*)d_in[11];
    const float* W2    = (const float*)d_in[12];
    const float* b2    = (const float*)d_in[13];
    const float* Wcb   = (const float*)d_in[14];
    const float* bcb   = (const float*)d_in[15];
    const float* Wf    = (const float*)d_in[16];
    const float* bf    = (const float*)d_in[17];
    float* out = (float*)d_out;

    cudaFuncSetAttribute(flow_kernel,
                         cudaFuncAttributeMaxDynamicSharedMemorySize,
                         (int)SMEM_BYTES);

    feat_kernel<<<N_ELEM, 256>>>(trend, seasonal, Wt, bt, Ws, bs, out);
    flow_kernel<<<GRID_FLOW, NT, SMEM_BYTES>>>(residual, binit, Wc0, bc0,
                                               W1, b1, W2, b2, Wcb, bcb,
                                               Wf, bf, out);
}

// round 4
// speedup vs baseline: 1.7334x; 1.7334x over previous
#include <cuda_runtime.h>
#include <math.h>

// ---------------------------------------------------------------------------
// Problem constants
// ---------------------------------------------------------------------------
#define T_LEN   2048
#define D_DIM   512
#define HH      64
#define S_STEPS 3
#define N_ELEM  65536
#define ROW_W   1025

// GEMM-tiled flow kernel config: 128 threads, 128 elements per CTA,
// thread tile = 8 rows x 8 elements.
#define NT      128
#define E_PER   128
#define GRID_FLOW (N_ELEM / E_PER)      // 512

// Shared layout (float offsets)
#define OFF_A   0                        // h_raw   [64][128]
#define OFF_B   8192                     // relu'd h / relu'd t [64][128]
#define OFF_W   16384                    // dup'd weights: u64 [64][66] = 8448 floats
#define WRP     66
#define OFF_SV  24832                    // step vectors, double buffered
#define SV_WC0  0
#define SV_B0   64
#define SV_B1   128
#define SV_B2   256
#define SV_WCB  384
#define SV_BCB  512
#define SV_WF   640
#define SV_BF   768
#define SV_SZ   776
#define OFF_CC  (OFF_SV + 2 * SV_SZ)     // 26384: cc[128]
#define OFF_TR  (OFF_CC + 128)           // trend[128]
#define OFF_SS  (OFF_TR + 128)           // seasonal[128]
#define SMEM_FLOATS (OFF_SS + 128)       // 26768
#define SMEM_BYTES  (SMEM_FLOATS * sizeof(float))   // 107,072 B -> 2 CTAs/SM

typedef unsigned long long ull;

__device__ __forceinline__ ull fma2(ull a, ull b, ull c) {
    ull d;
    asm("fma.rn.f32x2 %0, %1, %2, %3;" : "=l"(d) : "l"(a), "l"(b), "l"(c));
    return d;
}
__device__ __forceinline__ ull pack2(float x, float y) {
    ull r; asm("mov.b64 %0, {%1, %2};" : "=l"(r) : "f"(x), "f"(y)); return r;
}
__device__ __forceinline__ float2 unpack2(ull v) {
    float2 r; asm("mov.b64 {%0, %1}, %2;" : "=f"(r.x), "=f"(r.y) : "l"(v)); return r;
}

// Load 32 floats (one 64x64 matrix / 128 threads) coalesced into regs.
__device__ __forceinline__ void load_w(float4 w[8], const float* g, int tid) {
    const float4* gp = (const float4*)g;
#pragma unroll
    for (int q = 0; q < 8; q++) w[q] = gp[q * 128 + tid];
}

// Store regs as duplicated f32x2 pairs, transposed: SW[j*WRP + i] = (W[i][j], W[i][j])
__device__ __forceinline__ void sts_wdup(ull* SW, const float4 w[8], int tid) {
#pragma unroll
    for (int q = 0; q < 8; q++) {
        const int f = q * 128 + tid;       // float4 index
        const int i = f >> 4;              // row (output idx)
        const int j = (f & 15) << 2;       // col (k idx)
        SW[(j + 0) * WRP + i] = pack2(w[q].x, w[q].x);
        SW[(j + 1) * WRP + i] = pack2(w[q].y, w[q].y);
        SW[(j + 2) * WRP + i] = pack2(w[q].z, w[q].z);
        SW[(j + 3) * WRP + i] = pack2(w[q].w, w[q].w);
    }
}

// 64x64 @ 64x128 register-tiled GEMM: acc[8 rows][4 elem-pairs]
__device__ __forceinline__ void gemm_k64(ull acc[8][4], const float* smB,
                                         const ull* SW, int rg, int eg) {
#pragma unroll 4
    for (int k = 0; k < 64; k++) {
        const ulonglong2* ap = (const ulonglong2*)(SW + k * WRP + rg * 8);
        const ulonglong2 A0 = ap[0], A1 = ap[1], A2 = ap[2], A3 = ap[3];
        const ulonglong2* bp = (const ulonglong2*)(smB + k * E_PER + eg * 8);
        const ulonglong2 B0 = bp[0], B1 = bp[1];
        const ull av[8] = {A0.x, A0.y, A1.x, A1.y, A2.x, A2.y, A3.x, A3.y};
        const ull bv[4] = {B0.x, B0.y, B1.x, B1.y};
#pragma unroll
        for (int r = 0; r < 8; r++)
#pragma unroll
            for (int m = 0; m < 4; m++)
                acc[r][m] = fma2(av[r], bv[m], acc[r][m]);
    }
}

__global__ void __launch_bounds__(NT, 2)
fused_kernel(const float* __restrict__ trend, const float* __restrict__ seasonal,
             const float* __restrict__ residual,
             const float* __restrict__ Wt, const float* __restrict__ bt,
             const float* __restrict__ Ws, const float* __restrict__ bs,
             const float* __restrict__ gbinit, const float* __restrict__ gWc0,
             const float* __restrict__ gbc0,
             const float* __restrict__ gW1,   const float* __restrict__ gb1,
             const float* __restrict__ gW2,   const float* __restrict__ gb2,
             const float* __restrict__ gWcb,  const float* __restrict__ gbcb,
             const float* __restrict__ gWf,   const float* __restrict__ gbf,
             float* __restrict__ out)
{
    extern __shared__ float sm[];
    ull* SW = (ull*)(sm + OFF_W);
    const int tid = threadIdx.x;
    const int eg  = tid & 15;      // element group (8 elems)
    const int rg  = tid >> 4;      // row group (8 rows)
    const int e0  = blockIdx.x * E_PER;

    // ---- prologue: per-element state + feat weights + first weight stage ----
    const int eglob = e0 + tid;
    float z    = residual[eglob];
    float ldet = 0.0f;
    sm[OFF_CC + tid] = ((eglob & (T_LEN - 1)) == 0) ? 0.0f : residual[eglob - 1];
    sm[OFF_TR + tid] = trend[eglob];
    sm[OFF_SS + tid] = seasonal[eglob];

    // feat: thread owns cols {q*128+tid}, q=0..7 (q<4 trend, else seasonal)
    float fw[8], fbv[8];
#pragma unroll
    for (int q = 0; q < 8; q++) {
        const int c = q * 128 + tid;
        fw[q]  = (q < 4) ? Wt[c] : Ws[c - D_DIM];
        fbv[q] = (q < 4) ? bt[c] : bs[c - D_DIM];
    }

    float4 wpre[8];
    load_w(wpre, gW1, tid);        // W1[0]
    sts_wdup(SW, wpre, tid);
    load_w(wpre, gW2, tid);        // prefetch W2[0]

    // stage step-0 vectors into SV buffer 0
    {
        float* SVp = sm + OFF_SV;
        if (tid < 64) {
            SVp[SV_WC0 + tid] = gWc0[tid];
            SVp[SV_B0  + tid] = gbc0[tid] + gbinit[tid];
        }
        SVp[SV_B1  + tid] = gb1 [tid];
        SVp[SV_B2  + tid] = gb2 [tid];
        SVp[SV_WCB + tid] = gWcb[tid];
        SVp[SV_BCB + tid] = gbcb[tid];
        SVp[SV_WF  + tid] = gWf [tid];
        if (tid < 2) SVp[SV_BF + tid] = gbf[tid];
    }
    __syncthreads();

    int fch = 0;   // feat store progress: 8 chunks x 16 rows

    for (int s = 0; s < S_STEPS; s++) {
        const float* SVp = sm + OFF_SV + (s & 1) * SV_SZ;

        // ---- h-init: h = cc*wc0 + b0 -> A (raw), B (relu) ----
        {
            const ulonglong2* cp = (const ulonglong2*)(sm + OFF_CC + eg * 8);
            const ulonglong2 C0 = cp[0], C1 = cp[1];
            const ull ccp[4] = {C0.x, C0.y, C1.x, C1.y};
#pragma unroll
            for (int r = 0; r < 8; r++) {
                const int row = rg * 8 + r;
                const ull wd = pack2(SVp[SV_WC0 + row], SVp[SV_WC0 + row]);
                const ull bd = pack2(SVp[SV_B0 + row],  SVp[SV_B0 + row]);
                ull hv[4];
#pragma unroll
                for (int m = 0; m < 4; m++) hv[m] = fma2(ccp[m], wd, bd);
                ulonglong2* arow = (ulonglong2*)(sm + OFF_A + row * E_PER + eg * 8);
                arow[0] = make_ulonglong2(hv[0], hv[1]);
                arow[1] = make_ulonglong2(hv[2], hv[3]);
                float4* brow = (float4*)(sm + OFF_B + row * E_PER + eg * 8);
#pragma unroll
                for (int h2 = 0; h2 < 2; h2++) {
                    float2 p = unpack2(hv[2 * h2]), q = unpack2(hv[2 * h2 + 1]);
                    brow[h2] = make_float4(fmaxf(p.x, 0.f), fmaxf(p.y, 0.f),
                                           fmaxf(q.x, 0.f), fmaxf(q.y, 0.f));
                }
            }
        }
        __syncthreads();

        for (int blk = 0; blk < 2; blk++) {
            const int mi  = s * 2 + blk;
            const int nmi = (mi + 1 > 5) ? 5 : (mi + 1);

            // ---- GEMM1: t = W1 @ relu(h) + b1 ----
            ull acc[8][4];
#pragma unroll
            for (int r = 0; r < 8; r++) {
                const float b = SVp[SV_B1 + blk * 64 + rg * 8 + r];
                const ull bd = pack2(b, b);
#pragma unroll
                for (int m = 0; m < 4; m++) acc[r][m] = bd;
            }
            gemm_k64(acc, sm + OFF_B, SW, rg, eg);
            __syncthreads();

            // ---- epi1: stage W2 -> SW, relu(t) -> B, prefetch next W1 ----
            sts_wdup(SW, wpre, tid);                 // wpre == W2[mi]
#pragma unroll
            for (int r = 0; r < 8; r++) {
                const int row = rg * 8 + r;
                float4* brow = (float4*)(sm + OFF_B + row * E_PER + eg * 8);
#pragma unroll
                for (int h2 = 0; h2 < 2; h2++) {
                    float2 p = unpack2(acc[r][2 * h2]), q = unpack2(acc[r][2 * h2 + 1]);
                    brow[h2] = make_float4(fmaxf(p.x, 0.f), fmaxf(p.y, 0.f),
                                           fmaxf(q.x, 0.f), fmaxf(q.y, 0.f));
                }
            }
            load_w(wpre, gW1 + nmi * 4096, tid);     // prefetch W1[mi+1]
            if (fch < 8) {                           // feat chunk
                const int r0 = fch * 16; fch++;
                for (int e = r0; e < r0 + 16; e++) {
                    const float tv = sm[OFF_TR + e], sv2 = sm[OFF_SS + e];
                    float* orow = out + (size_t)(e0 + e) * ROW_W;
#pragma unroll
                    for (int q = 0; q < 8; q++)
                        orow[q * 128 + tid] = fmaf(q < 4 ? tv : sv2, fw[q], fbv[q]);
                }
            }
            __syncthreads();

            // ---- GEMM2: v = W2 @ relu(t) + b2 ----
#pragma unroll
            for (int r = 0; r < 8; r++) {
                const float b = SVp[SV_B2 + blk * 64 + rg * 8 + r];
                const ull bd = pack2(b, b);
#pragma unroll
                for (int m = 0; m < 4; m++) acc[r][m] = bd;
            }
            gemm_k64(acc, sm + OFF_B, SW, rg, eg);
            __syncthreads();

            // ---- epi2: stage next W1 -> SW, gate h += v*sig(g), prefetch W2 ----
            sts_wdup(SW, wpre, tid);                 // wpre == W1[mi+1]
            {
                const ulonglong2* cp = (const ulonglong2*)(sm + OFF_CC + eg * 8);
                const ulonglong2 C0 = cp[0], C1 = cp[1];
                const ull ccp[4] = {C0.x, C0.y, C1.x, C1.y};
#pragma unroll
                for (int r = 0; r < 8; r++) {
                    const int row = rg * 8 + r;
                    const float wcbv = SVp[SV_WCB + blk * 64 + row];
                    const float bcbv = SVp[SV_BCB + blk * 64 + row];
                    const ull wd = pack2(wcbv, wcbv), bd = pack2(bcbv, bcbv);
                    ulonglong2* arow = (ulonglong2*)(sm + OFF_A + row * E_PER + eg * 8);
                    const ulonglong2 H0 = arow[0], H1 = arow[1];
                    ull hv[4] = {H0.x, H0.y, H1.x, H1.y};
#pragma unroll
                    for (int m = 0; m < 4; m++) {
                        const float2 g = unpack2(fma2(ccp[m], wd, bd));
                        const float s0 = __fdividef(1.0f, 1.0f + __expf(-g.x));
                        const float s1 = __fdividef(1.0f, 1.0f + __expf(-g.y));
                        hv[m] = fma2(acc[r][m], pack2(s0, s1), hv[m]);
                    }
                    arow[0] = make_ulonglong2(hv[0], hv[1]);
                    arow[1] = make_ulonglong2(hv[2], hv[3]);
                    float4* brow = (float4*)(sm + OFF_B + row * E_PER + eg * 8);
#pragma unroll
                    for (int h2 = 0; h2 < 2; h2++) {
                        float2 p = unpack2(hv[2 * h2]), q = unpack2(hv[2 * h2 + 1]);
                        brow[h2] = make_float4(fmaxf(p.x, 0.f), fmaxf(p.y, 0.f),
                                               fmaxf(q.x, 0.f), fmaxf(q.y, 0.f));
                    }
                }
            }
            load_w(wpre, gW2 + nmi * 4096, tid);     // prefetch W2[mi+1]
            if (fch < 8) {                           // feat chunk
                const int r0 = fch * 16; fch++;
                for (int e = r0; e < r0 + 16; e++) {
                    const float tv = sm[OFF_TR + e], sv2 = sm[OFF_SS + e];
                    float* orow = out + (size_t)(e0 + e) * ROW_W;
#pragma unroll
                    for (int q = 0; q < 8; q++)
                        orow[q * 128 + tid] = fmaf(q < 4 ? tv : sv2, fw[q], fbv[q]);
                }
            }
            __syncthreads();
        }

        // ---- final linear (H->2) + z update; thread == element ----
        {
            float o0 = SVp[SV_BF + 0], o1 = SVp[SV_BF + 1];
#pragma unroll 4
            for (int j = 0; j < HH; j++) {
                const float rh = sm[OFF_B + j * E_PER + tid];
                o0 = fmaf(rh, SVp[SV_WF + j],      o0);
                o1 = fmaf(rh, SVp[SV_WF + 64 + j], o1);
            }
            const float sc = log1pf(__expf(o0)) + 1e-3f;
            z = fmaf(sc, z, o1);
            ldet += logf(sc);
        }
        // stage next step's vectors into the other SV buffer (no race: other buf)
        if (s < S_STEPS - 1) {
            float* SVn = sm + OFF_SV + ((s + 1) & 1) * SV_SZ;
            const int sn = s + 1;
            if (tid < 64) {
                SVn[SV_WC0 + tid] = gWc0[sn * 64 + tid];
                SVn[SV_B0  + tid] = gbc0[sn * 64 + tid] + gbinit[sn * 64 + tid];
            }
            SVn[SV_B1  + tid] = gb1 [sn * 128 + tid];
            SVn[SV_B2  + tid] = gb2 [sn * 128 + tid];
            SVn[SV_WCB + tid] = gWcb[sn * 128 + tid];
            SVn[SV_BCB + tid] = gbcb[sn * 128 + tid];
            SVn[SV_WF  + tid] = gWf [sn * 128 + tid];
            if (tid < 2) SVn[SV_BF + tid] = gbf[sn * 2 + tid];
        }
        __syncthreads();
    }

    // ---- log-prob store ----
    const float lp = fmaf(-0.5f * z, z, ldet) - 0.91893853320467274f;
    out[(size_t)eglob * ROW_W + 2 * D_DIM] = lp;

    // any leftover feat chunks (shouldn't trigger: 12 sites >= 8 chunks)
    while (fch < 8) {
        const int r0 = fch * 16; fch++;
        for (int e = r0; e < r0 + 16; e++) {
            const float tv = sm[OFF_TR + e], sv2 = sm[OFF_SS + e];
            float* orow = out + (size_t)(e0 + e) * ROW_W;
#pragma unroll
            for (int q = 0; q < 8; q++)
                orow[q * 128 + tid] = fmaf(q < 4 ? tv : sv2, fw[q], fbv[q]);
        }
    }
}

// ---------------------------------------------------------------------------
extern "C" void kernel_launch(void* const* d_in, const int* in_sizes, int n_in,
                              void* d_out, int out_size)
{
    const float* trend    = (const float*)d_in[0];
    const float* seasonal = (const float*)d_in[1];
    const float* residual = (const float*)d_in[2];
    const float* Wt    = (const float*)d_in[3];
    const float* bt    = (const float*)d_in[4];
    const float* Ws    = (const float*)d_in[5];
    const float* bs    = (const float*)d_in[6];
    const float* binit = (const float*)d_in[7];
    const float* Wc0   = (const float*)d_in[8];
    const float* bc0   = (const float*)d_in[9];
    const float* W1    = (const float*)d_in[10];
    const float* b1    = (const float*)d_in[11];
    const float* W2    = (const float*)d_in[12];
    const float* b2    = (const float*)d_in[13];
    const float* Wcb   = (const float*)d_in[14];
    const float* bcb   = (const float*)d_in[15];
    const float* Wf    = (const float*)d_in[16];
    const float* bf    = (const float*)d_in[17];
    float* out = (float*)d_out;

    cudaFuncSetAttribute(fused_kernel,
                         cudaFuncAttributeMaxDynamicSharedMemorySize,
                         (int)SMEM_BYTES);

    fused_kernel<<<GRID_FLOW, NT, SMEM_BYTES>>>(trend, seasonal, residual,
                                                Wt, bt, Ws, bs,
                                                binit, Wc0, bc0,
                                                W1, b1, W2, b2, Wcb, bcb,
                                                Wf, bf, out);
}

// round 9
// speedup vs baseline: 1.7468x; 1.0077x over previous
#include <cuda_runtime.h>
#include <math.h>

// ---------------------------------------------------------------------------
// Problem constants
// ---------------------------------------------------------------------------
#define T_LEN   2048
#define D_DIM   512
#define HH      64
#define S_STEPS 3
#define N_ELEM  65536
#define ROW_W   1025

// GEMM-tiled flow kernel config: 128 threads, 128 elements per CTA,
// thread tile = 8 rows x 8 elements.
#define NT      128
#define E_PER   128
#define GRID_FLOW (N_ELEM / E_PER)      // 512

// Shared layout (float offsets)
#define OFF_A   0                        // h_raw   [64][128]
#define OFF_B   8192                     // relu'd h / relu'd t [64][128]
#define OFF_W   16384                    // dup'd weights: u64 [64][66] = 8448 floats
#define WRP     66
#define OFF_SV  24832                    // step vectors, double buffered
#define SV_WC0  0
#define SV_B0   64
#define SV_B1   128
#define SV_B2   256
#define SV_WCB  384
#define SV_BCB  512
#define SV_WF   640
#define SV_BF   768
#define SV_SZ   776
#define OFF_CC  (OFF_SV + 2 * SV_SZ)     // 26384: cc[128]
#define OFF_TR  (OFF_CC + 128)           // trend[128]
#define OFF_SS  (OFF_TR + 128)           // seasonal[128]
#define SMEM_FLOATS (OFF_SS + 128)       // 26768
#define SMEM_BYTES  (SMEM_FLOATS * sizeof(float))   // 107,072 B -> 2 CTAs/SM

typedef unsigned long long ull;

__device__ __forceinline__ ull fma2(ull a, ull b, ull c) {
    ull d;
    asm("fma.rn.f32x2 %0, %1, %2, %3;" : "=l"(d) : "l"(a), "l"(b), "l"(c));
    return d;
}
__device__ __forceinline__ ull pack2(float x, float y) {
    ull r; asm("mov.b64 %0, {%1, %2};" : "=l"(r) : "f"(x), "f"(y)); return r;
}
__device__ __forceinline__ float2 unpack2(ull v) {
    float2 r; asm("mov.b64 {%0, %1}, %2;" : "=f"(r.x), "=f"(r.y) : "l"(v)); return r;
}

// ---------------------------------------------------------------------------
// Weight staging, transposed-friendly:
// thread (jt = tid>>3, oct = tid&7) handles chunks c=0..3:
//   j = c*16 + jt (k-index), holds W[oct*8+d][j] for d=0..7.
// Global read: strided scalar LDG, one base pointer + immediate offsets
// (weights are tiny and L2-resident after the first wave).
// ---------------------------------------------------------------------------
__device__ __forceinline__ void load_w(float w[32], const float* g, int tid) {
    const int jt  = tid >> 3;
    const int oct = tid & 7;
    const float* base = g + oct * 512 + jt;   // (oct*8+d)*64 + j = oct*512 + d*64 + c*16 + jt
#pragma unroll
    for (int c = 0; c < 4; c++)
#pragma unroll
        for (int d = 0; d < 8; d++)
            w[c * 8 + d] = base[c * 16 + d * 64];
}

// Store as duplicated f32x2 pairs, transposed: SW[j*WRP + i] = (W[i][j], W[i][j]).
// Each thread stores i-contiguous runs of 8 ull -> 4 STS.128 per chunk at the
// 4-phase floor (bases cover 8 distinct banks x 4 lanes).
__device__ __forceinline__ void sts_wdup(ull* SW, const float w[32], int tid) {
    const int jt  = tid >> 3;
    const int oct = tid & 7;
#pragma unroll
    for (int c = 0; c < 4; c++) {
        const int j = c * 16 + jt;
        ulonglong2* base = (ulonglong2*)(SW + j * WRP + oct * 8);
#pragma unroll
        for (int d2 = 0; d2 < 4; d2++) {
            const float a = w[c * 8 + 2 * d2], b = w[c * 8 + 2 * d2 + 1];
            base[d2] = make_ulonglong2(pack2(a, a), pack2(b, b));
        }
    }
}

// 64x64 @ 64x128 register-tiled GEMM: acc[8 rows][4 elem-pairs]
__device__ __forceinline__ void gemm_k64(ull acc[8][4], const float* smB,
                                         const ull* SW, int rg, int eg) {
#pragma unroll 4
    for (int k = 0; k < 64; k++) {
        const ulonglong2* ap = (const ulonglong2*)(SW + k * WRP + rg * 8);
        const ulonglong2 A0 = ap[0], A1 = ap[1], A2 = ap[2], A3 = ap[3];
        const ulonglong2* bp = (const ulonglong2*)(smB + k * E_PER + eg * 8);
        const ulonglong2 B0 = bp[0], B1 = bp[1];
        const ull av[8] = {A0.x, A0.y, A1.x, A1.y, A2.x, A2.y, A3.x, A3.y};
        const ull bv[4] = {B0.x, B0.y, B1.x, B1.y};
#pragma unroll
        for (int r = 0; r < 8; r++)
#pragma unroll
            for (int m = 0; m < 4; m++)
                acc[r][m] = fma2(av[r], bv[m], acc[r][m]);
    }
}

__global__ void __launch_bounds__(NT, 2)
fused_kernel(const float* __restrict__ trend, const float* __restrict__ seasonal,
             const float* __restrict__ residual,
             const float* __restrict__ Wt, const float* __restrict__ bt,
             const float* __restrict__ Ws, const float* __restrict__ bs,
             const float* __restrict__ gbinit, const float* __restrict__ gWc0,
             const float* __restrict__ gbc0,
             const float* __restrict__ gW1,   const float* __restrict__ gb1,
             const float* __restrict__ gW2,   const float* __restrict__ gb2,
             const float* __restrict__ gWcb,  const float* __restrict__ gbcb,
             const float* __restrict__ gWf,   const float* __restrict__ gbf,
             float* __restrict__ out)
{
    extern __shared__ float sm[];
    ull* SW = (ull*)(sm + OFF_W);
    const int tid = threadIdx.x;
    const int eg  = tid & 15;      // element group (8 elems)
    const int rg  = tid >> 4;      // row group (8 rows)
    const int e0  = blockIdx.x * E_PER;

    // ---- prologue: per-element state + feat weights + first weight stage ----
    const int eglob = e0 + tid;
    float z    = residual[eglob];
    float ldet = 0.0f;
    sm[OFF_CC + tid] = ((eglob & (T_LEN - 1)) == 0) ? 0.0f : residual[eglob - 1];
    sm[OFF_TR + tid] = trend[eglob];
    sm[OFF_SS + tid] = seasonal[eglob];

    // feat: thread owns cols {q*128+tid}, q=0..7 (q<4 trend, else seasonal)
    float fw[8], fbv[8];
#pragma unroll
    for (int q = 0; q < 8; q++) {
        const int c = q * 128 + tid;
        fw[q]  = (q < 4) ? Wt[c] : Ws[c - D_DIM];
        fbv[q] = (q < 4) ? bt[c] : bs[c - D_DIM];
    }

    float wpre[32];
    load_w(wpre, gW1, tid);        // W1[0]
    sts_wdup(SW, wpre, tid);
    load_w(wpre, gW2, tid);        // prefetch W2[0]

    // stage step-0 vectors into SV buffer 0
    {
        float* SVp = sm + OFF_SV;
        if (tid < 64) {
            SVp[SV_WC0 + tid] = gWc0[tid];
            SVp[SV_B0  + tid] = gbc0[tid] + gbinit[tid];
        }
        SVp[SV_B1  + tid] = gb1 [tid];
        SVp[SV_B2  + tid] = gb2 [tid];
        SVp[SV_WCB + tid] = gWcb[tid];
        SVp[SV_BCB + tid] = gbcb[tid];
        SVp[SV_WF  + tid] = gWf [tid];
        if (tid < 2) SVp[SV_BF + tid] = gbf[tid];
    }
    __syncthreads();

    int fch = 0;   // feat store progress: 8 chunks x 16 rows

    for (int s = 0; s < S_STEPS; s++) {
        const float* SVp = sm + OFF_SV + (s & 1) * SV_SZ;

        // ---- h-init: h = cc*wc0 + b0 -> A (raw), B (relu) ----
        {
            const ulonglong2* cp = (const ulonglong2*)(sm + OFF_CC + eg * 8);
            const ulonglong2 C0 = cp[0], C1 = cp[1];
            const ull ccp[4] = {C0.x, C0.y, C1.x, C1.y};
#pragma unroll
            for (int r = 0; r < 8; r++) {
                const int row = rg * 8 + r;
                const ull wd = pack2(SVp[SV_WC0 + row], SVp[SV_WC0 + row]);
                const ull bd = pack2(SVp[SV_B0 + row],  SVp[SV_B0 + row]);
                ull hv[4];
#pragma unroll
                for (int m = 0; m < 4; m++) hv[m] = fma2(ccp[m], wd, bd);
                ulonglong2* arow = (ulonglong2*)(sm + OFF_A + row * E_PER + eg * 8);
                arow[0] = make_ulonglong2(hv[0], hv[1]);
                arow[1] = make_ulonglong2(hv[2], hv[3]);
                float4* brow = (float4*)(sm + OFF_B + row * E_PER + eg * 8);
#pragma unroll
                for (int h2 = 0; h2 < 2; h2++) {
                    float2 p = unpack2(hv[2 * h2]), q = unpack2(hv[2 * h2 + 1]);
                    brow[h2] = make_float4(fmaxf(p.x, 0.f), fmaxf(p.y, 0.f),
                                           fmaxf(q.x, 0.f), fmaxf(q.y, 0.f));
                }
            }
        }
        __syncthreads();

        for (int blk = 0; blk < 2; blk++) {
            const int mi  = s * 2 + blk;
            const int nmi = (mi + 1 > 5) ? 5 : (mi + 1);

            // ---- feat chunk in the GEMM's fma shadow (no hazards) ----
            if (fch < 8) {
                const int r0 = fch * 16; fch++;
                for (int e = r0; e < r0 + 16; e++) {
                    const float tv = sm[OFF_TR + e], sv2 = sm[OFF_SS + e];
                    float* orow = out + (size_t)(e0 + e) * ROW_W;
#pragma unroll
                    for (int q = 0; q < 8; q++)
                        orow[q * 128 + tid] = fmaf(q < 4 ? tv : sv2, fw[q], fbv[q]);
                }
            }

            // ---- GEMM1: t = W1 @ relu(h) + b1 ----
            ull acc[8][4];
#pragma unroll
            for (int r = 0; r < 8; r++) {
                const float b = SVp[SV_B1 + blk * 64 + rg * 8 + r];
                const ull bd = pack2(b, b);
#pragma unroll
                for (int m = 0; m < 4; m++) acc[r][m] = bd;
            }
            gemm_k64(acc, sm + OFF_B, SW, rg, eg);
            __syncthreads();

            // ---- epi1: stage W2 -> SW, relu(t) -> B, prefetch next W1 ----
            sts_wdup(SW, wpre, tid);                 // wpre == W2[mi]
#pragma unroll
            for (int r = 0; r < 8; r++) {
                const int row = rg * 8 + r;
                float4* brow = (float4*)(sm + OFF_B + row * E_PER + eg * 8);
#pragma unroll
                for (int h2 = 0; h2 < 2; h2++) {
                    float2 p = unpack2(acc[r][2 * h2]), q = unpack2(acc[r][2 * h2 + 1]);
                    brow[h2] = make_float4(fmaxf(p.x, 0.f), fmaxf(p.y, 0.f),
                                           fmaxf(q.x, 0.f), fmaxf(q.y, 0.f));
                }
            }
            load_w(wpre, gW1 + nmi * 4096, tid);     // prefetch W1[mi+1]
            __syncthreads();

            // ---- feat chunk in GEMM2's fma shadow ----
            if (fch < 8) {
                const int r0 = fch * 16; fch++;
                for (int e = r0; e < r0 + 16; e++) {
                    const float tv = sm[OFF_TR + e], sv2 = sm[OFF_SS + e];
                    float* orow = out + (size_t)(e0 + e) * ROW_W;
#pragma unroll
                    for (int q = 0; q < 8; q++)
                        orow[q * 128 + tid] = fmaf(q < 4 ? tv : sv2, fw[q], fbv[q]);
                }
            }

            // ---- GEMM2: v = W2 @ relu(t) + b2 ----
#pragma unroll
            for (int r = 0; r < 8; r++) {
                const float b = SVp[SV_B2 + blk * 64 + rg * 8 + r];
                const ull bd = pack2(b, b);
#pragma unroll
                for (int m = 0; m < 4; m++) acc[r][m] = bd;
            }
            gemm_k64(acc, sm + OFF_B, SW, rg, eg);
            __syncthreads();

            // ---- epi2: stage next W1 -> SW, gate h += v*sig(g), prefetch W2 ----
            sts_wdup(SW, wpre, tid);                 // wpre == W1[mi+1]
            {
                const ulonglong2* cp = (const ulonglong2*)(sm + OFF_CC + eg * 8);
                const ulonglong2 C0 = cp[0], C1 = cp[1];
                const ull ccp[4] = {C0.x, C0.y, C1.x, C1.y};
#pragma unroll
                for (int r = 0; r < 8; r++) {
                    const int row = rg * 8 + r;
                    const float wcbv = SVp[SV_WCB + blk * 64 + row];
                    const float bcbv = SVp[SV_BCB + blk * 64 + row];
                    const ull wd = pack2(wcbv, wcbv), bd = pack2(bcbv, bcbv);
                    ulonglong2* arow = (ulonglong2*)(sm + OFF_A + row * E_PER + eg * 8);
                    const ulonglong2 H0 = arow[0], H1 = arow[1];
                    ull hv[4] = {H0.x, H0.y, H1.x, H1.y};
#pragma unroll
                    for (int m = 0; m < 4; m++) {
                        const float2 g = unpack2(fma2(ccp[m], wd, bd));
                        const float s0 = __fdividef(1.0f, 1.0f + __expf(-g.x));
                        const float s1 = __fdividef(1.0f, 1.0f + __expf(-g.y));
                        hv[m] = fma2(acc[r][m], pack2(s0, s1), hv[m]);
                    }
                    arow[0] = make_ulonglong2(hv[0], hv[1]);
                    arow[1] = make_ulonglong2(hv[2], hv[3]);
                    float4* brow = (float4*)(sm + OFF_B + row * E_PER + eg * 8);
#pragma unroll
                    for (int h2 = 0; h2 < 2; h2++) {
                        float2 p = unpack2(hv[2 * h2]), q = unpack2(hv[2 * h2 + 1]);
                        brow[h2] = make_float4(fmaxf(p.x, 0.f), fmaxf(p.y, 0.f),
                                               fmaxf(q.x, 0.f), fmaxf(q.y, 0.f));
                    }
                }
            }
            load_w(wpre, gW2 + nmi * 4096, tid);     // prefetch W2[mi+1]
            __syncthreads();
        }

        // ---- final linear (H->2) + z update; thread == element ----
        {
            float o0 = SVp[SV_BF + 0], o1 = SVp[SV_BF + 1];
#pragma unroll 4
            for (int j = 0; j < HH; j++) {
                const float rh = sm[OFF_B + j * E_PER + tid];
                o0 = fmaf(rh, SVp[SV_WF + j],      o0);
                o1 = fmaf(rh, SVp[SV_WF + 64 + j], o1);
            }
            const float sc = log1pf(__expf(o0)) + 1e-3f;
            z = fmaf(sc, z, o1);
            ldet += logf(sc);
        }
        // stage next step's vectors into the other SV buffer (no race: other buf)
        if (s < S_STEPS - 1) {
            float* SVn = sm + OFF_SV + ((s + 1) & 1) * SV_SZ;
            const int sn = s + 1;
            if (tid < 64) {
                SVn[SV_WC0 + tid] = gWc0[sn * 64 + tid];
                SVn[SV_B0  + tid] = gbc0[sn * 64 + tid] + gbinit[sn * 64 + tid];
            }
            SVn[SV_B1  + tid] = gb1 [sn * 128 + tid];
            SVn[SV_B2  + tid] = gb2 [sn * 128 + tid];
            SVn[SV_WCB + tid] = gWcb[sn * 128 + tid];
            SVn[SV_BCB + tid] = gbcb[sn * 128 + tid];
            SVn[SV_WF  + tid] = gWf [sn * 128 + tid];
            if (tid < 2) SVn[SV_BF + tid] = gbf[sn * 2 + tid];
        }
        __syncthreads();
    }

    // ---- log-prob store ----
    const float lp = fmaf(-0.5f * z, z, ldet) - 0.91893853320467274f;
    out[(size_t)eglob * ROW_W + 2 * D_DIM] = lp;

    // any leftover feat chunks (shouldn't trigger: 12 sites >= 8 chunks)
    while (fch < 8) {
        const int r0 = fch * 16; fch++;
        for (int e = r0; e < r0 + 16; e++) {
            const float tv = sm[OFF_TR + e], sv2 = sm[OFF_SS + e];
            float* orow = out + (size_t)(e0 + e) * ROW_W;
#pragma unroll
            for (int q = 0; q < 8; q++)
                orow[q * 128 + tid] = fmaf(q < 4 ? tv : sv2, fw[q], fbv[q]);
        }
    }
}

// ---------------------------------------------------------------------------
extern "C" void kernel_launch(void* const* d_in, const int* in_sizes, int n_in,
                              void* d_out, int out_size)
{
    const float* trend    = (const float*)d_in[0];
    const float* seasonal = (const float*)d_in[1];
    const float* residual = (const float*)d_in[2];
    const float* Wt    = (const float*)d_in[3];
    const float* bt    = (const float*)d_in[4];
    const float* Ws    = (const float*)d_in[5];
    const float* bs    = (const float*)d_in[6];
    const float* binit = (const float*)d_in[7];
    const float* Wc0   = (const float*)d_in[8];
    const float* bc0   = (const float*)d_in[9];
    const float* W1    = (const float*)d_in[10];
    const float* b1    = (const float*)d_in[11];
    const float* W2    = (const float*)d_in[12];
    const float* b2    = (const float*)d_in[13];
    const float* Wcb   = (const float*)d_in[14];
    const float* bcb   = (const float*)d_in[15];
    const float* Wf    = (const float*)d_in[16];
    const float* bf    = (const float*)d_in[17];
    float* out = (float*)d_out;

    cudaFuncSetAttribute(fused_kernel,
                         cudaFuncAttributeMaxDynamicSharedMemorySize,
                         (int)SMEM_BYTES);

    fused_kernel<<<GRID_FLOW, NT, SMEM_BYTES>>>(trend, seasonal, residual,
                                                Wt, bt, Ws, bs,
                                                binit, Wc0, bc0,
                                                W1, b1, W2, b2, Wcb, bcb,
                                                Wf, bf, out);
}

// round 11
// speedup vs baseline: 2.0344x; 1.1646x over previous
#include <cuda_runtime.h>
#include <math.h>

// ---------------------------------------------------------------------------
// Problem constants
// ---------------------------------------------------------------------------
#define T_LEN   2048
#define D_DIM   512
#define HH      64
#define S_STEPS 3
#define N_ELEM  65536
#define ROW_W   1025

// GEMM-tiled flow kernel config: 128 threads, 128 elements per CTA,
// thread tile = 8 rows x 8 elements.
#define NT      128
#define E_PER   128
#define GRID_FLOW (N_ELEM / E_PER)      // 512

// Shared layout (float offsets)
#define OFF_A   0                        // h_raw   [64][128]
#define OFF_B   8192                     // relu'd h / relu'd t [64][128]
#define OFF_W   16384                    // transposed weights (NON-dup floats)
#define WRP     68                       // row stride in floats (16B-aligned)
#define OFF_SV  (OFF_W + HH * WRP)       // 16384 + 4352 = 20736
#define SV_WC0  0
#define SV_B0   64
#define SV_B1   128
#define SV_B2   256
#define SV_WCB  384
#define SV_BCB  512
#define SV_WF   640
#define SV_BF   768
#define SV_SZ   776
#define OFF_CC  (OFF_SV + 2 * SV_SZ)     // cc[128]
#define OFF_TR  (OFF_CC + 128)
#define OFF_SS  (OFF_TR + 128)
#define SMEM_FLOATS (OFF_SS + 128)       // 22672
#define SMEM_BYTES  (SMEM_FLOATS * sizeof(float))   // 90,688 B -> 2 CTAs/SM

typedef unsigned long long ull;

__device__ __forceinline__ ull fma2(ull a, ull b, ull c) {
    ull d;
    asm("fma.rn.f32x2 %0, %1, %2, %3;" : "=l"(d) : "l"(a), "l"(b), "l"(c));
    return d;
}
__device__ __forceinline__ ull pack2(float x, float y) {
    ull r; asm("mov.b64 %0, {%1, %2};" : "=l"(r) : "f"(x), "f"(y)); return r;
}
__device__ __forceinline__ float2 unpack2(ull v) {
    float2 r; asm("mov.b64 {%0, %1}, %2;" : "=f"(r.x), "=f"(r.y) : "l"(v)); return r;
}

// ---------------------------------------------------------------------------
// Weight staging: thread (jt = tid>>3, oct = tid&7) handles chunks c=0..3:
//   j = c*16 + jt (k-index), holds W[oct*8+d][j] for d=0..7.
// ---------------------------------------------------------------------------
__device__ __forceinline__ void load_w(float w[32], const float* g, int tid) {
    const int jt  = tid >> 3;
    const int oct = tid & 7;
    const float* base = g + oct * 512 + jt;
#pragma unroll
    for (int c = 0; c < 4; c++)
#pragma unroll
        for (int d = 0; d < 8; d++)
            w[c * 8 + d] = base[c * 16 + d * 64];
}

// Plain transposed float store (NO duplication): SW[j*WRP + i] = W[i][j].
// Each thread stores two float4 runs per chunk.
__device__ __forceinline__ void sts_wt(float* SW, const float w[32], int tid) {
    const int jt  = tid >> 3;
    const int oct = tid & 7;
#pragma unroll
    for (int c = 0; c < 4; c++) {
        const int j = c * 16 + jt;
        float4* base = (float4*)(SW + j * WRP + oct * 8);
        base[0] = make_float4(w[c * 8 + 0], w[c * 8 + 1], w[c * 8 + 2], w[c * 8 + 3]);
        base[1] = make_float4(w[c * 8 + 4], w[c * 8 + 5], w[c * 8 + 6], w[c * 8 + 7]);
    }
}

// 64x64 @ 64x128 register-tiled GEMM: acc[8 rows][4 elem-pairs].
// A loaded as 32B unique data (2x LDS.128), duplicated into (a,a) pairs via
// ALU movs -- crossbar wavefronts per k drop 24 -> 16.
__device__ __forceinline__ void gemm_k64(ull acc[8][4], const float* smB,
                                         const float* SW, int rg, int eg) {
#pragma unroll 4
    for (int k = 0; k < 64; k++) {
        const float4* ap = (const float4*)(SW + k * WRP + rg * 8);
        const float4 A0 = ap[0], A1 = ap[1];
        const ulonglong2* bp = (const ulonglong2*)(smB + k * E_PER + eg * 8);
        const ulonglong2 B0 = bp[0], B1 = bp[1];
        ull av[8];
        av[0] = pack2(A0.x, A0.x); av[1] = pack2(A0.y, A0.y);
        av[2] = pack2(A0.z, A0.z); av[3] = pack2(A0.w, A0.w);
        av[4] = pack2(A1.x, A1.x); av[5] = pack2(A1.y, A1.y);
        av[6] = pack2(A1.z, A1.z); av[7] = pack2(A1.w, A1.w);
        const ull bv[4] = {B0.x, B0.y, B1.x, B1.y};
#pragma unroll
        for (int r = 0; r < 8; r++)
#pragma unroll
            for (int m = 0; m < 4; m++)
                acc[r][m] = fma2(av[r], bv[m], acc[r][m]);
    }
}

__global__ void __launch_bounds__(NT, 2)
fused_kernel(const float* __restrict__ trend, const float* __restrict__ seasonal,
             const float* __restrict__ residual,
             const float* __restrict__ Wt, const float* __restrict__ bt,
             const float* __restrict__ Ws, const float* __restrict__ bs,
             const float* __restrict__ gbinit, const float* __restrict__ gWc0,
             const float* __restrict__ gbc0,
             const float* __restrict__ gW1,   const float* __restrict__ gb1,
             const float* __restrict__ gW2,   const float* __restrict__ gb2,
             const float* __restrict__ gWcb,  const float* __restrict__ gbcb,
             const float* __restrict__ gWf,   const float* __restrict__ gbf,
             float* __restrict__ out)
{
    extern __shared__ float sm[];
    float* SW = sm + OFF_W;
    const int tid = threadIdx.x;
    const int eg  = tid & 15;      // element group (8 elems)
    const int rg  = tid >> 4;      // row group (8 rows)
    const int e0  = blockIdx.x * E_PER;

    // ---- prologue ----
    const int eglob = e0 + tid;
    float z    = residual[eglob];
    float ldet = 0.0f;
    sm[OFF_CC + tid] = ((eglob & (T_LEN - 1)) == 0) ? 0.0f : residual[eglob - 1];
    sm[OFF_TR + tid] = trend[eglob];
    sm[OFF_SS + tid] = seasonal[eglob];

    float fw[8], fbv[8];
#pragma unroll
    for (int q = 0; q < 8; q++) {
        const int c = q * 128 + tid;
        fw[q]  = (q < 4) ? Wt[c] : Ws[c - D_DIM];
        fbv[q] = (q < 4) ? bt[c] : bs[c - D_DIM];
    }

    float wpre[32];
    load_w(wpre, gW1, tid);        // W1[0]
    sts_wt(SW, wpre, tid);
    load_w(wpre, gW2, tid);        // prefetch W2[0]

    {
        float* SVp = sm + OFF_SV;
        if (tid < 64) {
            SVp[SV_WC0 + tid] = gWc0[tid];
            SVp[SV_B0  + tid] = gbc0[tid] + gbinit[tid];
        }
        SVp[SV_B1  + tid] = gb1 [tid];
        SVp[SV_B2  + tid] = gb2 [tid];
        SVp[SV_WCB + tid] = gWcb[tid];
        SVp[SV_BCB + tid] = gbcb[tid];
        SVp[SV_WF  + tid] = gWf [tid];
        if (tid < 2) SVp[SV_BF + tid] = gbf[tid];
    }
    __syncthreads();

    int fch = 0;   // feat store progress: 8 chunks x 16 rows

    for (int s = 0; s < S_STEPS; s++) {
        const float* SVp = sm + OFF_SV + (s & 1) * SV_SZ;

        // ---- h-init: h = cc*wc0 + b0 -> A (raw), B (relu) ----
        {
            const ulonglong2* cp = (const ulonglong2*)(sm + OFF_CC + eg * 8);
            const ulonglong2 C0 = cp[0], C1 = cp[1];
            const ull ccp[4] = {C0.x, C0.y, C1.x, C1.y};
#pragma unroll
            for (int r = 0; r < 8; r++) {
                const int row = rg * 8 + r;
                const ull wd = pack2(SVp[SV_WC0 + row], SVp[SV_WC0 + row]);
                const ull bd = pack2(SVp[SV_B0 + row],  SVp[SV_B0 + row]);
                ull hv[4];
#pragma unroll
                for (int m = 0; m < 4; m++) hv[m] = fma2(ccp[m], wd, bd);
                ulonglong2* arow = (ulonglong2*)(sm + OFF_A + row * E_PER + eg * 8);
                arow[0] = make_ulonglong2(hv[0], hv[1]);
                arow[1] = make_ulonglong2(hv[2], hv[3]);
                float4* brow = (float4*)(sm + OFF_B + row * E_PER + eg * 8);
#pragma unroll
                for (int h2 = 0; h2 < 2; h2++) {
                    float2 p = unpack2(hv[2 * h2]), q = unpack2(hv[2 * h2 + 1]);
                    brow[h2] = make_float4(fmaxf(p.x, 0.f), fmaxf(p.y, 0.f),
                                           fmaxf(q.x, 0.f), fmaxf(q.y, 0.f));
                }
            }
        }
        __syncthreads();

        for (int blk = 0; blk < 2; blk++) {
            const int mi  = s * 2 + blk;
            const int nmi = (mi + 1 > 5) ? 5 : (mi + 1);

            // ---- feat chunk (overlapped with GEMM phase) ----
            if (fch < 8) {
                const int r0 = fch * 16; fch++;
                for (int e = r0; e < r0 + 16; e++) {
                    const float tv = sm[OFF_TR + e], sv2 = sm[OFF_SS + e];
                    float* orow = out + (size_t)(e0 + e) * ROW_W;
#pragma unroll
                    for (int q = 0; q < 8; q++)
                        orow[q * 128 + tid] = fmaf(q < 4 ? tv : sv2, fw[q], fbv[q]);
                }
            }

            // ---- GEMM1: t = W1 @ relu(h) + b1 ----
            ull acc[8][4];
#pragma unroll
            for (int r = 0; r < 8; r++) {
                const float b = SVp[SV_B1 + blk * 64 + rg * 8 + r];
                const ull bd = pack2(b, b);
#pragma unroll
                for (int m = 0; m < 4; m++) acc[r][m] = bd;
            }
            gemm_k64(acc, sm + OFF_B, SW, rg, eg);
            __syncthreads();

            // ---- epi1: stage W2 -> SW, relu(t) -> B, prefetch next W1 ----
            sts_wt(SW, wpre, tid);                   // wpre == W2[mi]
#pragma unroll
            for (int r = 0; r < 8; r++) {
                const int row = rg * 8 + r;
                float4* brow = (float4*)(sm + OFF_B + row * E_PER + eg * 8);
#pragma unroll
                for (int h2 = 0; h2 < 2; h2++) {
                    float2 p = unpack2(acc[r][2 * h2]), q = unpack2(acc[r][2 * h2 + 1]);
                    brow[h2] = make_float4(fmaxf(p.x, 0.f), fmaxf(p.y, 0.f),
                                           fmaxf(q.x, 0.f), fmaxf(q.y, 0.f));
                }
            }
            load_w(wpre, gW1 + nmi * 4096, tid);     // prefetch W1[mi+1]
            __syncthreads();

            // ---- feat chunk ----
            if (fch < 8) {
                const int r0 = fch * 16; fch++;
                for (int e = r0; e < r0 + 16; e++) {
                    const float tv = sm[OFF_TR + e], sv2 = sm[OFF_SS + e];
                    float* orow = out + (size_t)(e0 + e) * ROW_W;
#pragma unroll
                    for (int q = 0; q < 8; q++)
                        orow[q * 128 + tid] = fmaf(q < 4 ? tv : sv2, fw[q], fbv[q]);
                }
            }

            // ---- GEMM2: v = W2 @ relu(t) + b2 ----
#pragma unroll
            for (int r = 0; r < 8; r++) {
                const float b = SVp[SV_B2 + blk * 64 + rg * 8 + r];
                const ull bd = pack2(b, b);
#pragma unroll
                for (int m = 0; m < 4; m++) acc[r][m] = bd;
            }
            gemm_k64(acc, sm + OFF_B, SW, rg, eg);
            __syncthreads();

            // ---- epi2: stage next W1, gate h += v*sig(g), prefetch W2 ----
            sts_wt(SW, wpre, tid);                   // wpre == W1[mi+1]
            {
                const ulonglong2* cp = (const ulonglong2*)(sm + OFF_CC + eg * 8);
                const ulonglong2 C0 = cp[0], C1 = cp[1];
                const ull ccp[4] = {C0.x, C0.y, C1.x, C1.y};
#pragma unroll
                for (int r = 0; r < 8; r++) {
                    const int row = rg * 8 + r;
                    const float wcbv = SVp[SV_WCB + blk * 64 + row];
                    const float bcbv = SVp[SV_BCB + blk * 64 + row];
                    const ull wd = pack2(wcbv, wcbv), bd = pack2(bcbv, bcbv);
                    ulonglong2* arow = (ulonglong2*)(sm + OFF_A + row * E_PER + eg * 8);
                    const ulonglong2 H0 = arow[0], H1 = arow[1];
                    ull hv[4] = {H0.x, H0.y, H1.x, H1.y};
#pragma unroll
                    for (int m = 0; m < 4; m++) {
                        const float2 g = unpack2(fma2(ccp[m], wd, bd));
                        const float s0 = __fdividef(1.0f, 1.0f + __expf(-g.x));
                        const float s1 = __fdividef(1.0f, 1.0f + __expf(-g.y));
                        hv[m] = fma2(acc[r][m], pack2(s0, s1), hv[m]);
                    }
                    arow[0] = make_ulonglong2(hv[0], hv[1]);
                    arow[1] = make_ulonglong2(hv[2], hv[3]);
                    float4* brow = (float4*)(sm + OFF_B + row * E_PER + eg * 8);
#pragma unroll
                    for (int h2 = 0; h2 < 2; h2++) {
                        float2 p = unpack2(hv[2 * h2]), q = unpack2(hv[2 * h2 + 1]);
                        brow[h2] = make_float4(fmaxf(p.x, 0.f), fmaxf(p.y, 0.f),
                                               fmaxf(q.x, 0.f), fmaxf(q.y, 0.f));
                    }
                }
            }
            load_w(wpre, gW2 + nmi * 4096, tid);     // prefetch W2[mi+1]
            __syncthreads();
        }

        // ---- final linear (H->2) + z update; thread == element ----
        {
            float o0 = SVp[SV_BF + 0], o1 = SVp[SV_BF + 1];
#pragma unroll 4
            for (int j = 0; j < HH; j++) {
                const float rh = sm[OFF_B + j * E_PER + tid];
                o0 = fmaf(rh, SVp[SV_WF + j],      o0);
                o1 = fmaf(rh, SVp[SV_WF + 64 + j], o1);
            }
            const float sc = log1pf(__expf(o0)) + 1e-3f;
            z = fmaf(sc, z, o1);
            ldet += logf(sc);
        }
        // stage next step's vectors into the other SV buffer
        if (s < S_STEPS - 1) {
            float* SVn = sm + OFF_SV + ((s + 1) & 1) * SV_SZ;
            const int sn = s + 1;
            if (tid < 64) {
                SVn[SV_WC0 + tid] = gWc0[sn * 64 + tid];
                SVn[SV_B0  + tid] = gbc0[sn * 64 + tid] + gbinit[sn * 64 + tid];
            }
            SVn[SV_B1  + tid] = gb1 [sn * 128 + tid];
            SVn[SV_B2  + tid] = gb2 [sn * 128 + tid];
            SVn[SV_WCB + tid] = gWcb[sn * 128 + tid];
            SVn[SV_BCB + tid] = gbcb[sn * 128 + tid];
            SVn[SV_WF  + tid] = gWf [sn * 128 + tid];
            if (tid < 2) SVn[SV_BF + tid] = gbf[sn * 2 + tid];
        }
        __syncthreads();
    }

    // ---- log-prob store ----
    const float lp = fmaf(-0.5f * z, z, ldet) - 0.91893853320467274f;
    out[(size_t)eglob * ROW_W + 2 * D_DIM] = lp;

    // leftover feat chunks (shouldn't trigger)
    while (fch < 8) {
        const int r0 = fch * 16; fch++;
        for (int e = r0; e < r0 + 16; e++) {
            const float tv = sm[OFF_TR + e], sv2 = sm[OFF_SS + e];
            float* orow = out + (size_t)(e0 + e) * ROW_W;
#pragma unroll
            for (int q = 0; q < 8; q++)
                orow[q * 128 + tid] = fmaf(q < 4 ? tv : sv2, fw[q], fbv[q]);
        }
    }
}

// ---------------------------------------------------------------------------
extern "C" void kernel_launch(void* const* d_in, const int* in_sizes, int n_in,
                              void* d_out, int out_size)
{
    const float* trend    = (const float*)d_in[0];
    const float* seasonal = (const float*)d_in[1];
    const float* residual = (const float*)d_in[2];
    const float* Wt    = (const float*)d_in[3];
    const float* bt    = (const float*)d_in[4];
    const float* Ws    = (const float*)d_in[5];
    const float* bs    = (const float*)d_in[6];
    const float* binit = (const float*)d_in[7];
    const float* Wc0   = (const float*)d_in[8];
    const float* bc0   = (const float*)d_in[9];
    const float* W1    = (const float*)d_in[10];
    const float* b1    = (const float*)d_in[11];
    const float* W2    = (const float*)d_in[12];
    const float* b2    = (const float*)d_in[13];
    const float* Wcb   = (const float*)d_in[14];
    const float* bcb   = (const float*)d_in[15];
    const float* Wf    = (const float*)d_in[16];
    const float* bf    = (const float*)d_in[17];
    float* out = (float*)d_out;

    cudaFuncSetAttribute(fused_kernel,
                         cudaFuncAttributeMaxDynamicSharedMemorySize,
                         (int)SMEM_BYTES);

    fused_kernel<<<GRID_FLOW, NT, SMEM_BYTES>>>(trend, seasonal, residual,
                                                Wt, bt, Ws, bs,
                                                binit, Wc0, bc0,
                                                W1, b1, W2, b2, Wcb, bcb,
                                                Wf, bf, out);
}

// round 12
// speedup vs baseline: 2.1167x; 1.0405x over previous
#include <cuda_runtime.h>
#include <math.h>

// ---------------------------------------------------------------------------
// Problem constants
// ---------------------------------------------------------------------------
#define T_LEN   2048
#define D_DIM   512
#define HH      64
#define S_STEPS 3
#define N_ELEM  65536
#define ROW_W   1025

// GEMM-tiled flow kernel config: 128 threads, 128 elements per CTA,
// thread tile = 8 rows x 8 elements. h-tile lives in registers.
#define NT      128
#define E_PER   128
#define GRID_FLOW (N_ELEM / E_PER)      // 512

// Shared layout (float offsets)
#define OFF_B   0                        // relu'd h / relu'd t [64][128]
#define OFF_W   8192                     // transposed weights (non-dup floats)
#define WRP     68                       // row stride (16B-aligned)
#define OFF_SV  (OFF_W + HH * WRP)       // 8192 + 4352 = 12544 (single buffer)
#define SV_WC0  0
#define SV_B0   64
#define SV_B1   128
#define SV_B2   256
#define SV_WCB  384
#define SV_BCB  512
#define SV_WF   640
#define SV_BF   768
#define SV_SZ   776
#define OFF_CC  (OFF_SV + SV_SZ)         // cc[128]
#define OFF_TR  (OFF_CC + 128)
#define OFF_SS  (OFF_TR + 128)
#define SMEM_FLOATS (OFF_SS + 128)       // 13704
#define SMEM_BYTES  (SMEM_FLOATS * sizeof(float))   // 54,816 B -> 3+ CTAs/SM

typedef unsigned long long ull;

__device__ __forceinline__ ull fma2(ull a, ull b, ull c) {
    ull d;
    asm("fma.rn.f32x2 %0, %1, %2, %3;" : "=l"(d) : "l"(a), "l"(b), "l"(c));
    return d;
}
__device__ __forceinline__ ull pack2(float x, float y) {
    ull r; asm("mov.b64 %0, {%1, %2};" : "=l"(r) : "f"(x), "f"(y)); return r;
}
__device__ __forceinline__ float2 unpack2(ull v) {
    float2 r; asm("mov.b64 {%0, %1}, %2;" : "=f"(r.x), "=f"(r.y) : "l"(v)); return r;
}

// ---------------------------------------------------------------------------
// Weight staging: thread (jt = tid>>3, oct = tid&7) handles chunks c=0..3:
//   j = c*16 + jt (k-index), holds W[oct*8+d][j] for d=0..7.
// ---------------------------------------------------------------------------
__device__ __forceinline__ void load_w(float w[32], const float* g, int tid) {
    const int jt  = tid >> 3;
    const int oct = tid & 7;
    const float* base = g + oct * 512 + jt;
#pragma unroll
    for (int c = 0; c < 4; c++)
#pragma unroll
        for (int d = 0; d < 8; d++)
            w[c * 8 + d] = base[c * 16 + d * 64];
}

// Plain transposed float store (no duplication): SW[j*WRP + i] = W[i][j].
__device__ __forceinline__ void sts_wt(float* SW, const float w[32], int tid) {
    const int jt  = tid >> 3;
    const int oct = tid & 7;
#pragma unroll
    for (int c = 0; c < 4; c++) {
        const int j = c * 16 + jt;
        float4* base = (float4*)(SW + j * WRP + oct * 8);
        base[0] = make_float4(w[c * 8 + 0], w[c * 8 + 1], w[c * 8 + 2], w[c * 8 + 3]);
        base[1] = make_float4(w[c * 8 + 4], w[c * 8 + 5], w[c * 8 + 6], w[c * 8 + 7]);
    }
}

// 64x64 @ 64x128 register-tiled GEMM: acc[8 rows][4 elem-pairs].
// A loaded as 32B unique data (2x LDS.128), dup'd to (a,a) pairs via ALU movs.
__device__ __forceinline__ void gemm_k64(ull acc[8][4], const float* smB,
                                         const float* SW, int rg, int eg) {
#pragma unroll 4
    for (int k = 0; k < 64; k++) {
        const float4* ap = (const float4*)(SW + k * WRP + rg * 8);
        const float4 A0 = ap[0], A1 = ap[1];
        const ulonglong2* bp = (const ulonglong2*)(smB + k * E_PER + eg * 8);
        const ulonglong2 B0 = bp[0], B1 = bp[1];
        ull av[8];
        av[0] = pack2(A0.x, A0.x); av[1] = pack2(A0.y, A0.y);
        av[2] = pack2(A0.z, A0.z); av[3] = pack2(A0.w, A0.w);
        av[4] = pack2(A1.x, A1.x); av[5] = pack2(A1.y, A1.y);
        av[6] = pack2(A1.z, A1.z); av[7] = pack2(A1.w, A1.w);
        const ull bv[4] = {B0.x, B0.y, B1.x, B1.y};
#pragma unroll
        for (int r = 0; r < 8; r++)
#pragma unroll
            for (int m = 0; m < 4; m++)
                acc[r][m] = fma2(av[r], bv[m], acc[r][m]);
    }
}

// Write relu of a packed 8x8 tile (4 hv-pairs per row) into the B buffer.
__device__ __forceinline__ void store_relu(float* smB, const ull hv[4],
                                           int row, int eg) {
    float4* brow = (float4*)(smB + row * E_PER + eg * 8);
#pragma unroll
    for (int h2 = 0; h2 < 2; h2++) {
        float2 p = unpack2(hv[2 * h2]), q = unpack2(hv[2 * h2 + 1]);
        brow[h2] = make_float4(fmaxf(p.x, 0.f), fmaxf(p.y, 0.f),
                               fmaxf(q.x, 0.f), fmaxf(q.y, 0.f));
    }
}

__global__ void __launch_bounds__(NT, 3)
fused_kernel(const float* __restrict__ trend, const float* __restrict__ seasonal,
             const float* __restrict__ residual,
             const float* __restrict__ Wt, const float* __restrict__ bt,
             const float* __restrict__ Ws, const float* __restrict__ bs,
             const float* __restrict__ gbinit, const float* __restrict__ gWc0,
             const float* __restrict__ gbc0,
             const float* __restrict__ gW1,   const float* __restrict__ gb1,
             const float* __restrict__ gW2,   const float* __restrict__ gb2,
             const float* __restrict__ gWcb,  const float* __restrict__ gbcb,
             const float* __restrict__ gWf,   const float* __restrict__ gbf,
             float* __restrict__ out)
{
    extern __shared__ float sm[];
    float* SW = sm + OFF_W;
    const int tid = threadIdx.x;
    const int eg  = tid & 15;      // element group (8 elems)
    const int rg  = tid >> 4;      // row group (8 rows)
    const int e0  = blockIdx.x * E_PER;

    // ---- prologue ----
    const int eglob = e0 + tid;
    float z    = residual[eglob];
    float ldet = 0.0f;
    sm[OFF_CC + tid] = ((eglob & (T_LEN - 1)) == 0) ? 0.0f : residual[eglob - 1];
    sm[OFF_TR + tid] = trend[eglob];
    sm[OFF_SS + tid] = seasonal[eglob];

    {   // stage W1[0]
        float wpre[32];
        load_w(wpre, gW1, tid);
        sts_wt(SW, wpre, tid);
    }
    {   // stage step-0 vectors
        float* SVp = sm + OFF_SV;
        if (tid < 64) {
            SVp[SV_WC0 + tid] = gWc0[tid];
            SVp[SV_B0  + tid] = gbc0[tid] + gbinit[tid];
        }
        SVp[SV_B1  + tid] = gb1 [tid];
        SVp[SV_B2  + tid] = gb2 [tid];
        SVp[SV_WCB + tid] = gWcb[tid];
        SVp[SV_BCB + tid] = gbcb[tid];
        SVp[SV_WF  + tid] = gWf [tid];
        if (tid < 2) SVp[SV_BF + tid] = gbf[tid];
    }
    __syncthreads();

    ull hreg[8][4];                // raw h tile, register-resident
    int fch = 0;                   // feat store progress: 8 chunks x 16 rows

    for (int s = 0; s < S_STEPS; s++) {
        const float* SVp = sm + OFF_SV;

        // ---- h-init: h = cc*wc0 + b0 -> hreg (raw), B (relu) ----
        {
            const ulonglong2* cp = (const ulonglong2*)(sm + OFF_CC + eg * 8);
            const ulonglong2 C0 = cp[0], C1 = cp[1];
            const ull ccp[4] = {C0.x, C0.y, C1.x, C1.y};
#pragma unroll
            for (int r = 0; r < 8; r++) {
                const int row = rg * 8 + r;
                const ull wd = pack2(SVp[SV_WC0 + row], SVp[SV_WC0 + row]);
                const ull bd = pack2(SVp[SV_B0 + row],  SVp[SV_B0 + row]);
#pragma unroll
                for (int m = 0; m < 4; m++) hreg[r][m] = fma2(ccp[m], wd, bd);
                store_relu(sm + OFF_B, hreg[r], row, eg);
            }
        }
        __syncthreads();

        for (int blk = 0; blk < 2; blk++) {
            const int mi  = s * 2 + blk;
            const int nmi = (mi + 1 > 5) ? 5 : (mi + 1);

            // ---- feat chunk (weights reloaded; L2-hot) ----
            if (fch < 8) {
                const int r0 = fch * 16; fch++;
                float wq[8], bq[8];
#pragma unroll
                for (int q = 0; q < 8; q++) {
                    const int c = q * 128 + tid;
                    wq[q] = (q < 4) ? Wt[c] : Ws[c - D_DIM];
                    bq[q] = (q < 4) ? bt[c] : bs[c - D_DIM];
                }
                for (int e = r0; e < r0 + 16; e++) {
                    const float tv = sm[OFF_TR + e], sv2 = sm[OFF_SS + e];
                    float* orow = out + (size_t)(e0 + e) * ROW_W;
#pragma unroll
                    for (int q = 0; q < 8; q++)
                        orow[q * 128 + tid] = fmaf(q < 4 ? tv : sv2, wq[q], bq[q]);
                }
            }

            // ---- GEMM1: t = W1 @ relu(h) + b1 ----
            ull acc[8][4];
#pragma unroll
            for (int r = 0; r < 8; r++) {
                const float b = SVp[SV_B1 + blk * 64 + rg * 8 + r];
                const ull bd = pack2(b, b);
#pragma unroll
                for (int m = 0; m < 4; m++) acc[r][m] = bd;
            }
            gemm_k64(acc, sm + OFF_B, SW, rg, eg);
            __syncthreads();

            // ---- epi1: LDG W2[mi], relu(t) -> B, stage W2 -> SW ----
            {
                float wpre[32];
                load_w(wpre, gW2 + mi * 4096, tid);
#pragma unroll
                for (int r = 0; r < 8; r++)
                    store_relu(sm + OFF_B, acc[r], rg * 8 + r, eg);
                sts_wt(SW, wpre, tid);
            }
            __syncthreads();

            // ---- GEMM2: v = W2 @ relu(t) + b2 ----
#pragma unroll
            for (int r = 0; r < 8; r++) {
                const float b = SVp[SV_B2 + blk * 64 + rg * 8 + r];
                const ull bd = pack2(b, b);
#pragma unroll
                for (int m = 0; m < 4; m++) acc[r][m] = bd;
            }
            gemm_k64(acc, sm + OFF_B, SW, rg, eg);
            __syncthreads();

            // ---- epi2: LDG W1[nmi], gate hreg += v*sig(g), relu -> B, stage ----
            {
                float wpre[32];
                load_w(wpre, gW1 + nmi * 4096, tid);
                const ulonglong2* cp = (const ulonglong2*)(sm + OFF_CC + eg * 8);
                const ulonglong2 C0 = cp[0], C1 = cp[1];
                const ull ccp[4] = {C0.x, C0.y, C1.x, C1.y};
#pragma unroll
                for (int r = 0; r < 8; r++) {
                    const int row = rg * 8 + r;
                    const float wcbv = SVp[SV_WCB + blk * 64 + row];
                    const float bcbv = SVp[SV_BCB + blk * 64 + row];
                    const ull wd = pack2(wcbv, wcbv), bd = pack2(bcbv, bcbv);
#pragma unroll
                    for (int m = 0; m < 4; m++) {
                        const float2 g = unpack2(fma2(ccp[m], wd, bd));
                        const float s0 = __fdividef(1.0f, 1.0f + __expf(-g.x));
                        const float s1 = __fdividef(1.0f, 1.0f + __expf(-g.y));
                        hreg[r][m] = fma2(acc[r][m], pack2(s0, s1), hreg[r][m]);
                    }
                    store_relu(sm + OFF_B, hreg[r], row, eg);
                }
                sts_wt(SW, wpre, tid);
            }
            __syncthreads();
        }

        // ---- final linear (H->2) + z update; thread == element ----
        {
            float o0 = SVp[SV_BF + 0], o1 = SVp[SV_BF + 1];
#pragma unroll 4
            for (int j = 0; j < HH; j++) {
                const float rh = sm[OFF_B + j * E_PER + tid];
                o0 = fmaf(rh, SVp[SV_WF + j],      o0);
                o1 = fmaf(rh, SVp[SV_WF + 64 + j], o1);
            }
            const float sc = log1pf(__expf(o0)) + 1e-3f;
            z = fmaf(sc, z, o1);
            ldet += logf(sc);
        }
        __syncthreads();   // all reads of SV done before restaging

        if (s < S_STEPS - 1) {
            float* SVn = sm + OFF_SV;
            const int sn = s + 1;
            if (tid < 64) {
                SVn[SV_WC0 + tid] = gWc0[sn * 64 + tid];
                SVn[SV_B0  + tid] = gbc0[sn * 64 + tid] + gbinit[sn * 64 + tid];
            }
            SVn[SV_B1  + tid] = gb1 [sn * 128 + tid];
            SVn[SV_B2  + tid] = gb2 [sn * 128 + tid];
            SVn[SV_WCB + tid] = gWcb[sn * 128 + tid];
            SVn[SV_BCB + tid] = gbcb[sn * 128 + tid];
            SVn[SV_WF  + tid] = gWf [sn * 128 + tid];
            if (tid < 2) SVn[SV_BF + tid] = gbf[sn * 2 + tid];
            __syncthreads();
        }
    }

    // ---- log-prob store ----
    const float lp = fmaf(-0.5f * z, z, ldet) - 0.91893853320467274f;
    out[(size_t)eglob * ROW_W + 2 * D_DIM] = lp;

    // leftover feat chunks (shouldn't trigger: 12 sites >= 8 chunks)
    while (fch < 8) {
        const int r0 = fch * 16; fch++;
        for (int e = r0; e < r0 + 16; e++) {
            const float tv = sm[OFF_TR + e], sv2 = sm[OFF_SS + e];
            float* orow = out + (size_t)(e0 + e) * ROW_W;
#pragma unroll
            for (int q = 0; q < 8; q++) {
                const int c = q * 128 + tid;
                const float w = (q < 4) ? Wt[c] : Ws[c - D_DIM];
                const float b = (q < 4) ? bt[c] : bs[c - D_DIM];
                orow[c] = fmaf(q < 4 ? tv : sv2, w, b);
            }
        }
    }
}

// ---------------------------------------------------------------------------
extern "C" void kernel_launch(void* const* d_in, const int* in_sizes, int n_in,
                              void* d_out, int out_size)
{
    const float* trend    = (const float*)d_in[0];
    const float* seasonal = (const float*)d_in[1];
    const float* residual = (const float*)d_in[2];
    const float* Wt    = (const float*)d_in[3];
    const float* bt    = (const float*)d_in[4];
    const float* Ws    = (const float*)d_in[5];
    const float* bs    = (const float*)d_in[6];
    const float* binit = (const float*)d_in[7];
    const float* Wc0   = (const float*)d_in[8];
    const float* bc0   = (const float*)d_in[9];
    const float* W1    = (const float*)d_in[10];
    const float* b1    = (const float*)d_in[11];
    const float* W2    = (const float*)d_in[12];
    const float* b2    = (const float*)d_in[13];
    const float* Wcb   = (const float*)d_in[14];
    const float* bcb   = (const float*)d_in[15];
    const float* Wf    = (const float*)d_in[16];
    const float* bf    = (const float*)d_in[17];
    float* out = (float*)d_out;

    cudaFuncSetAttribute(fused_kernel,
                         cudaFuncAttributeMaxDynamicSharedMemorySize,
                         (int)SMEM_BYTES);

    fused_kernel<<<GRID_FLOW, NT, SMEM_BYTES>>>(trend, seasonal, residual,
                                                Wt, bt, Ws, bs,
                                                binit, Wc0, bc0,
                                                W1, b1, W2, b2, Wcb, bcb,
                                                Wf, bf, out);
}

// round 16
// speedup vs baseline: 3.3365x; 1.5762x over previous
#include <cuda_runtime.h>
#include <cuda_bf16.h>
#include <stdint.h>
#include <math.h>

// ---------------------------------------------------------------------------
// Problem constants
// ---------------------------------------------------------------------------
#define T_LEN   2048
#define D_DIM   512
#define HH      64
#define S_STEPS 3
#define N_ELEM  65536
#define ROW_W   1025

#define NT      128
#define E_PER   128
#define GRID_FLOW (N_ELEM / E_PER)      // 512

// ---- smem byte layout (tile bases 1024-aligned for SW128 swizzle) ----
#define SM_AH0  0                        // act0 hi [128][64] bf16, 16KB
#define SM_AL0  16384
#define SM_AH1  32768                    // act1 (t) hi/lo
#define SM_AL1  49152
#define SM_WH1  65536                    // W1 slot hi/lo [64][64] bf16, 8KB
#define SM_WL1  73728
#define SM_WH2  81920                    // W2 slot hi/lo
#define SM_WL2  90112
#define SM_SV   98304                    // step vectors (float idx)
#define SV_WC0  0
#define SV_B0   64
#define SV_B1   128
#define SV_B2   256
#define SV_WCB  384
#define SV_BCB  512
#define SV_WF   640
#define SV_BF   768
#define SV_SZ   776
#define SM_CC   (SM_SV + SV_SZ * 4)      // cc[128] f32
#define SM_OZ   (SM_CC + 512)            // o0o1 [128][2] f32
#define SM_TR   (SM_OZ + 1024)
#define SM_SS   (SM_TR + 512)
#define SMEM_BYTES (SM_SS + 512)         // 103,968 B -> 2 CTAs/SM

#define SWZ(off) ((off) ^ (((off) >> 3) & 0x70))

static __device__ __forceinline__ uint32_t toff(int row, int col) {
    return SWZ((uint32_t)(row * 128 + col * 2));
}
static __device__ __forceinline__ float relu(float x) { return fmaxf(x, 0.0f); }

// mma.sync m16n8k16 row.col f32.bf16.bf16.f32 (sm_80 PTX -- valid on compute_103)
static __device__ __forceinline__ void mma16816(float c[4], const uint32_t a[4],
                                                uint32_t b0, uint32_t b1) {
    asm("mma.sync.aligned.m16n8k16.row.col.f32.bf16.bf16.f32 "
        "{%0,%1,%2,%3}, {%4,%5,%6,%7}, {%8,%9}, {%0,%1,%2,%3};"
        : "+f"(c[0]), "+f"(c[1]), "+f"(c[2]), "+f"(c[3])
        : "r"(a[0]), "r"(a[1]), "r"(a[2]), "r"(a[3]), "r"(b0), "r"(b1));
}

// Split a float pair into bf16x2 hi and bf16x2 lo words.
static __device__ __forceinline__ void cvt2(float a, float b,
                                            uint32_t& hi, uint32_t& lo) {
    __nv_bfloat16 ah = __float2bfloat16(a), bh = __float2bfloat16(b);
    float ar = a - __bfloat162float(ah);
    float br = b - __bfloat162float(bh);
    __nv_bfloat162 hp = __halves2bfloat162(ah, bh);
    __nv_bfloat162 lp = __floats2bfloat162_rn(ar, br);
    hi = *(uint32_t*)&hp;
    lo = *(uint32_t*)&lp;
}

// A fragment: rows row0+g / row0+g+8, k pair cols kbase+2tig, kbase+2tig+8
static __device__ __forceinline__ void ldA(uint32_t a[4], const char* t,
                                           int row0, int kbase, int g, int tig) {
    a[0] = *(const uint32_t*)(t + toff(row0 + g,     kbase + 2 * tig));
    a[1] = *(const uint32_t*)(t + toff(row0 + g + 8, kbase + 2 * tig));
    a[2] = *(const uint32_t*)(t + toff(row0 + g,     kbase + 2 * tig + 8));
    a[3] = *(const uint32_t*)(t + toff(row0 + g + 8, kbase + 2 * tig + 8));
}
// B fragment from W[n][k] tile: col n0+g, k pairs kbase+2tig / +8
static __device__ __forceinline__ void ldB(uint32_t& b0, uint32_t& b1,
                                           const char* t, int n0, int kbase,
                                           int g, int tig) {
    b0 = *(const uint32_t*)(t + toff(n0 + g, kbase + 2 * tig));
    b1 = *(const uint32_t*)(t + toff(n0 + g, kbase + 2 * tig + 8));
}

// Store relu'd C-fragment (4 f32) into hi/lo bf16 tiles at (row0, col0).
static __device__ __forceinline__ void st_frag_relu(char* TH, char* TL,
                                                    int row0, int col0,
                                                    int g, int tig,
                                                    const float c[4]) {
    uint32_t hi, lo;
    cvt2(relu(c[0]), relu(c[1]), hi, lo);
    uint32_t o = toff(row0 + g, col0 + 2 * tig);
    *(uint32_t*)(TH + o) = hi;  *(uint32_t*)(TL + o) = lo;
    cvt2(relu(c[2]), relu(c[3]), hi, lo);
    o = toff(row0 + g + 8, col0 + 2 * tig);
    *(uint32_t*)(TH + o) = hi;  *(uint32_t*)(TL + o) = lo;
}

// Stage a 64x64 fp32 weight matrix [n][k] as bf16 hi/lo SW128 tiles (128 thr).
static __device__ __forceinline__ void stage_w(char* smc, int hoff, int loff,
                                               const float* gW, int tid) {
    const int n  = tid >> 1;
    const int kh = (tid & 1) * 32;
    const float* gp = gW + n * 64 + kh;
#pragma unroll
    for (int c = 0; c < 4; c++) {
        float4 v0 = *(const float4*)(gp + c * 8);
        float4 v1 = *(const float4*)(gp + c * 8 + 4);
        uint32_t h0, l0, h1, l1, h2, l2, h3, l3;
        cvt2(v0.x, v0.y, h0, l0); cvt2(v0.z, v0.w, h1, l1);
        cvt2(v1.x, v1.y, h2, l2); cvt2(v1.z, v1.w, h3, l3);
        const uint32_t off = SWZ((uint32_t)(n * 128 + kh * 2 + c * 16));
        *(uint4*)(smc + hoff + off) = make_uint4(h0, h1, h2, h3);
        *(uint4*)(smc + loff + off) = make_uint4(l0, l1, l2, l3);
    }
}

// One N-half (32 cols) of a 128x64x64 split GEMM for this warp's 32 rows.
static __device__ __forceinline__ void gemm_half(float (&acc)[2][4][4],
                                                 const char* AH, const char* AL,
                                                 const char* WH, const char* WL,
                                                 int nh, int m0, int g, int tig) {
#pragma unroll
    for (int kt = 0; kt < 4; kt++) {
        const int kbase = kt * 16;
        uint32_t ah[2][4], al[2][4];
#pragma unroll
        for (int mt = 0; mt < 2; mt++) {
            ldA(ah[mt], AH, m0 + 16 * mt, kbase, g, tig);
            ldA(al[mt], AL, m0 + 16 * mt, kbase, g, tig);
        }
#pragma unroll
        for (int nt = 0; nt < 4; nt++) {
            const int n0 = nh * 32 + nt * 8;
            uint32_t bh0, bh1, bl0, bl1;
            ldB(bh0, bh1, WH, n0, kbase, g, tig);
            ldB(bl0, bl1, WL, n0, kbase, g, tig);
#pragma unroll
            for (int mt = 0; mt < 2; mt++) {
                mma16816(acc[mt][nt], ah[mt], bh0, bh1);
                mma16816(acc[mt][nt], al[mt], bh0, bh1);
                mma16816(acc[mt][nt], ah[mt], bl0, bl1);
            }
        }
    }
}

static __device__ __forceinline__ void feat_chunk(int fc, int e0, int tid,
    const float* smf_tr, const float* smf_ss,
    const float* __restrict__ Wt, const float* __restrict__ bt,
    const float* __restrict__ Ws, const float* __restrict__ bs,
    float* __restrict__ out) {
    const int r0 = fc * 16;
    float wq[8], bq[8];
#pragma unroll
    for (int q = 0; q < 8; q++) {
        const int c = q * 128 + tid;
        wq[q] = (q < 4) ? Wt[c] : Ws[c - D_DIM];
        bq[q] = (q < 4) ? bt[c] : bs[c - D_DIM];
    }
    for (int e = r0; e < r0 + 16; e++) {
        const float tv = smf_tr[e], sv2 = smf_ss[e];
        float* orow = out + (size_t)(e0 + e) * ROW_W;
#pragma unroll
        for (int q = 0; q < 8; q++)
            orow[q * 128 + tid] = fmaf(q < 4 ? tv : sv2, wq[q], bq[q]);
    }
}

__global__ void __launch_bounds__(NT, 2)
fused_kernel(const float* __restrict__ trend, const float* __restrict__ seasonal,
             const float* __restrict__ residual,
             const float* __restrict__ Wt, const float* __restrict__ bt,
             const float* __restrict__ Ws, const float* __restrict__ bs,
             const float* __restrict__ gbinit, const float* __restrict__ gWc0,
             const float* __restrict__ gbc0,
             const float* __restrict__ gW1,   const float* __restrict__ gb1,
             const float* __restrict__ gW2,   const float* __restrict__ gb2,
             const float* __restrict__ gWcb,  const float* __restrict__ gbcb,
             const float* __restrict__ gWf,   const float* __restrict__ gbf,
             float* __restrict__ out)
{
    extern __shared__ char smc[];
    float* SVp    = (float*)(smc + SM_SV);
    float* CC     = (float*)(smc + SM_CC);
    float* OZ     = (float*)(smc + SM_OZ);
    float* smf_tr = (float*)(smc + SM_TR);
    float* smf_ss = (float*)(smc + SM_SS);

    const int tid  = threadIdx.x;
    const int lane = tid & 31;
    const int g    = lane >> 2;
    const int tig  = lane & 3;
    const int m0   = (tid >> 5) * 32;    // warp's element-row base
    const int e0   = blockIdx.x * E_PER;
    const int eglob = e0 + tid;

    // ---- prologue ----
    float z    = residual[eglob];
    float ldet = 0.0f;
    CC[tid]     = ((eglob & (T_LEN - 1)) == 0) ? 0.0f : residual[eglob - 1];
    smf_tr[tid] = trend[eglob];
    smf_ss[tid] = seasonal[eglob];

    stage_w(smc, SM_WH1, SM_WL1, gW1, tid);
    stage_w(smc, SM_WH2, SM_WL2, gW2, tid);
    {
        if (tid < 64) {
            SVp[SV_WC0 + tid] = gWc0[tid];
            SVp[SV_B0  + tid] = gbc0[tid] + gbinit[tid];
        }
        SVp[SV_B1  + tid] = gb1 [tid];
        SVp[SV_B2  + tid] = gb2 [tid];
        SVp[SV_WCB + tid] = gWcb[tid];
        SVp[SV_BCB + tid] = gbcb[tid];
        SVp[SV_WF  + tid] = gWf [tid];
        if (tid < 2) SVp[SV_BF + tid] = gbf[tid];
    }
    __syncthreads();

    float h[2][8][4];      // raw h in C-fragment layout: [mt][ntile][j]
    int fch = 0;

    for (int s = 0; s < S_STEPS; s++) {
        // ---- h-init: h = cc*wc0 + b0 (frag layout), relu-split -> A0 ----
#pragma unroll
        for (int nt = 0; nt < 8; nt++) {
            const int n = nt * 8 + 2 * tig;
            const float wA = SVp[SV_WC0 + n], wB = SVp[SV_WC0 + n + 1];
            const float bA = SVp[SV_B0 + n],  bB = SVp[SV_B0 + n + 1];
#pragma unroll
            for (int mt = 0; mt < 2; mt++) {
                const float c0 = CC[m0 + 16 * mt + g];
                const float c1 = CC[m0 + 16 * mt + g + 8];
                h[mt][nt][0] = fmaf(c0, wA, bA);
                h[mt][nt][1] = fmaf(c0, wB, bB);
                h[mt][nt][2] = fmaf(c1, wA, bA);
                h[mt][nt][3] = fmaf(c1, wB, bB);
                st_frag_relu(smc + SM_AH0, smc + SM_AL0,
                             m0 + 16 * mt, nt * 8, g, tig, h[mt][nt]);
            }
        }
        __syncwarp();

        for (int blk = 0; blk < 2; blk++) {
            const int mi = 2 * s + blk;

            if (fch < 8) { feat_chunk(fch, e0, tid, smf_tr, smf_ss, Wt, bt, Ws, bs, out); fch++; }

            // ---- GEMM1: t = relu(h) @ W1^T + b1, relu-split -> A1 ----
#pragma unroll
            for (int nh = 0; nh < 2; nh++) {
                float acc[2][4][4];
#pragma unroll
                for (int mt = 0; mt < 2; mt++)
#pragma unroll
                    for (int nt = 0; nt < 4; nt++)
#pragma unroll
                        for (int j = 0; j < 4; j++) acc[mt][nt][j] = 0.0f;
                gemm_half(acc, smc + SM_AH0, smc + SM_AL0,
                          smc + SM_WH1, smc + SM_WL1, nh, m0, g, tig);
#pragma unroll
                for (int nt = 0; nt < 4; nt++) {
                    const int n = nh * 32 + nt * 8 + 2 * tig;
                    const float bA = SVp[SV_B1 + blk * 64 + n];
                    const float bB = SVp[SV_B1 + blk * 64 + n + 1];
#pragma unroll
                    for (int mt = 0; mt < 2; mt++) {
                        float c[4] = {acc[mt][nt][0] + bA, acc[mt][nt][1] + bB,
                                      acc[mt][nt][2] + bA, acc[mt][nt][3] + bB};
                        st_frag_relu(smc + SM_AH1, smc + SM_AL1,
                                     m0 + 16 * mt, nh * 32 + nt * 8, g, tig, c);
                    }
                }
            }
            __syncwarp();

            if (fch < 8) { feat_chunk(fch, e0, tid, smf_tr, smf_ss, Wt, bt, Ws, bs, out); fch++; }

            // ---- GEMM2 + gate: h += (relu(t)@W2^T + b2) * sigmoid(cc*wcb+bcb) ----
#pragma unroll
            for (int nh = 0; nh < 2; nh++) {
                float acc[2][4][4];
#pragma unroll
                for (int mt = 0; mt < 2; mt++)
#pragma unroll
                    for (int nt = 0; nt < 4; nt++)
#pragma unroll
                        for (int j = 0; j < 4; j++) acc[mt][nt][j] = 0.0f;
                gemm_half(acc, smc + SM_AH1, smc + SM_AL1,
                          smc + SM_WH2, smc + SM_WL2, nh, m0, g, tig);
#pragma unroll
                for (int nt = 0; nt < 4; nt++) {
                    const int n = nh * 32 + nt * 8 + 2 * tig;
                    const float b2A = SVp[SV_B2 + blk * 64 + n];
                    const float b2B = SVp[SV_B2 + blk * 64 + n + 1];
                    const float wcA = SVp[SV_WCB + blk * 64 + n];
                    const float wcB = SVp[SV_WCB + blk * 64 + n + 1];
                    const float bcA = SVp[SV_BCB + blk * 64 + n];
                    const float bcB = SVp[SV_BCB + blk * 64 + n + 1];
#pragma unroll
                    for (int mt = 0; mt < 2; mt++) {
                        const float c0 = CC[m0 + 16 * mt + g];
                        const float c1 = CC[m0 + 16 * mt + g + 8];
                        const float ga0 = fmaf(c0, wcA, bcA), gb0 = fmaf(c0, wcB, bcB);
                        const float ga1 = fmaf(c1, wcA, bcA), gb1v = fmaf(c1, wcB, bcB);
                        const float s0 = __fdividef(1.f, 1.f + __expf(-ga0));
                        const float s1 = __fdividef(1.f, 1.f + __expf(-gb0));
                        const float s2 = __fdividef(1.f, 1.f + __expf(-ga1));
                        const float s3 = __fdividef(1.f, 1.f + __expf(-gb1v));
                        float* hv = h[mt][nh * 4 + nt];
                        hv[0] = fmaf(acc[mt][nt][0] + b2A, s0, hv[0]);
                        hv[1] = fmaf(acc[mt][nt][1] + b2B, s1, hv[1]);
                        hv[2] = fmaf(acc[mt][nt][2] + b2A, s2, hv[2]);
                        hv[3] = fmaf(acc[mt][nt][3] + b2B, s3, hv[3]);
                    }
                }
            }
            // write relu(h) -> A0 for next blk's GEMM1 (skip after last blk)
            if (blk == 0) {
#pragma unroll
                for (int nt = 0; nt < 8; nt++)
#pragma unroll
                    for (int mt = 0; mt < 2; mt++)
                        st_frag_relu(smc + SM_AH0, smc + SM_AL0,
                                     m0 + 16 * mt, nt * 8, g, tig, h[mt][nt]);
            }
            __syncwarp();

            // restage weights for next mi (block-wide)
            __syncthreads();
            if (mi < 5) {
                stage_w(smc, SM_WH1, SM_WL1, gW1 + (mi + 1) * 4096, tid);
                stage_w(smc, SM_WH2, SM_WL2, gW2 + (mi + 1) * 4096, tid);
                __syncthreads();
            }
        }

        // ---- final linear (H->2) in frag layout + shfl reduce ----
        {
            float fo[2][2][2];   // [mt][rowhalf][o]
#pragma unroll
            for (int mt = 0; mt < 2; mt++)
#pragma unroll
                for (int rh2 = 0; rh2 < 2; rh2++)
                    fo[mt][rh2][0] = fo[mt][rh2][1] = 0.0f;
#pragma unroll
            for (int nt = 0; nt < 8; nt++) {
                const int n = nt * 8 + 2 * tig;
                const float w0A = SVp[SV_WF + n],      w0B = SVp[SV_WF + n + 1];
                const float w1A = SVp[SV_WF + 64 + n], w1B = SVp[SV_WF + 64 + n + 1];
#pragma unroll
                for (int mt = 0; mt < 2; mt++) {
                    const float r0 = relu(h[mt][nt][0]), r1 = relu(h[mt][nt][1]);
                    const float r2 = relu(h[mt][nt][2]), r3 = relu(h[mt][nt][3]);
                    fo[mt][0][0] += r0 * w0A + r1 * w0B;
                    fo[mt][0][1] += r0 * w1A + r1 * w1B;
                    fo[mt][1][0] += r2 * w0A + r3 * w0B;
                    fo[mt][1][1] += r2 * w1A + r3 * w1B;
                }
            }
#pragma unroll
            for (int mt = 0; mt < 2; mt++)
#pragma unroll
                for (int rh2 = 0; rh2 < 2; rh2++)
#pragma unroll
                    for (int o = 0; o < 2; o++) {
                        float v = fo[mt][rh2][o];
                        v += __shfl_xor_sync(0xffffffffu, v, 1);
                        v += __shfl_xor_sync(0xffffffffu, v, 2);
                        fo[mt][rh2][o] = v;
                    }
            if (tig == 0) {
#pragma unroll
                for (int mt = 0; mt < 2; mt++)
#pragma unroll
                    for (int rh2 = 0; rh2 < 2; rh2++) {
                        const int row = m0 + 16 * mt + rh2 * 8 + g;
                        OZ[row * 2 + 0] = fo[mt][rh2][0];
                        OZ[row * 2 + 1] = fo[mt][rh2][1];
                    }
            }
            __syncwarp();
            const float o0 = OZ[tid * 2 + 0] + SVp[SV_BF + 0];
            const float o1 = OZ[tid * 2 + 1] + SVp[SV_BF + 1];
            const float sc = log1pf(__expf(o0)) + 1e-3f;
            z = fmaf(sc, z, o1);
            ldet += logf(sc);
        }

        // restage step vectors
        __syncthreads();
        if (s < S_STEPS - 1) {
            const int sn = s + 1;
            if (tid < 64) {
                SVp[SV_WC0 + tid] = gWc0[sn * 64 + tid];
                SVp[SV_B0  + tid] = gbc0[sn * 64 + tid] + gbinit[sn * 64 + tid];
            }
            SVp[SV_B1  + tid] = gb1 [sn * 128 + tid];
            SVp[SV_B2  + tid] = gb2 [sn * 128 + tid];
            SVp[SV_WCB + tid] = gWcb[sn * 128 + tid];
            SVp[SV_BCB + tid] = gbcb[sn * 128 + tid];
            SVp[SV_WF  + tid] = gWf [sn * 128 + tid];
            if (tid < 2) SVp[SV_BF + tid] = gbf[sn * 2 + tid];
            __syncthreads();
        }
    }

    // ---- log-prob store ----
    const float lp = fmaf(-0.5f * z, z, ldet) - 0.91893853320467274f;
    out[(size_t)eglob * ROW_W + 2 * D_DIM] = lp;

    // leftover feat chunks (12 slots >= 8; shouldn't trigger)
    while (fch < 8) {
        feat_chunk(fch, e0, tid, smf_tr, smf_ss, Wt, bt, Ws, bs, out);
        fch++;
    }
}

// ---------------------------------------------------------------------------
extern "C" void kernel_launch(void* const* d_in, const int* in_sizes, int n_in,
                              void* d_out, int out_size)
{
    const float* trend    = (const float*)d_in[0];
    const float* seasonal = (const float*)d_in[1];
    const float* residual = (const float*)d_in[2];
    const float* Wt    = (const float*)d_in[3];
    const float* bt    = (const float*)d_in[4];
    const float* Ws    = (const float*)d_in[5];
    const float* bs    = (const float*)d_in[6];
    const float* binit = (const float*)d_in[7];
    const float* Wc0   = (const float*)d_in[8];
    const float* bc0   = (const float*)d_in[9];
    const float* W1    = (const float*)d_in[10];
    const float* b1    = (const float*)d_in[11];
    const float* W2    = (const float*)d_in[12];
    const float* b2    = (const float*)d_in[13];
    const float* Wcb   = (const float*)d_in[14];
    const float* bcb   = (const float*)d_in[15];
    const float* Wf    = (const float*)d_in[16];
    const float* bf    = (const float*)d_in[17];
    float* out = (float*)d_out;

    cudaFuncSetAttribute(fused_kernel,
                         cudaFuncAttributeMaxDynamicSharedMemorySize,
                         (int)SMEM_BYTES);

    fused_kernel<<<GRID_FLOW, NT, SMEM_BYTES>>>(trend, seasonal, residual,
                                                Wt, bt, Ws, bs,
                                                binit, Wc0, bc0,
                                                W1, b1, W2, b2, Wcb, bcb,
                                                Wf, bf, out);
}